// round 9
// baseline (speedup 1.0000x reference)
#include <cuda_runtime.h>
#include <cuda_bf16.h>
#include <mma.h>
#include <cstdint>
#include <math.h>

using namespace nvcuda;

// ===========================================================================
// WeightedPermuteMLP — split-bf16 wmma, double-buffered smem (BK=16).
// B=8, SEG=16, DIM=1024, HID=256.  5 GEMMs M=32768, N=K=1024.
// fp32 loads (proven addressing) -> register split bf16 hi/lo -> smem -> wmma.
// D = Ah*Bh + Ah*Bl + Al*Bh (fp32 accum), rel_err ~1e-5.
// Mainloop: one __syncthreads per chunk; cvt/store overlaps MMA compute.
// ===========================================================================

#define NELEM 33554432

__device__ __align__(256) float g_h[NELEM];
__device__ __align__(256) float g_w[NELEM];
__device__ __align__(256) float g_d[NELEM];
__device__ __align__(256) float g_c[NELEM];
__device__ __align__(256) float g_partial[8 * 32 * 1024];
__device__ __align__(256) float g_sum[8 * 1024];
__device__ __align__(256) float g_a[4 * 8 * 1024];   // [q][b][chan]

__device__ __forceinline__ int row_base(int m, int s1, int s2, int s3) {
    return (m >> 12) * 4194304 + ((m >> 8) & 15) * s1 + ((m >> 4) & 15) * s2 + (m & 15) * s3;
}

// split 8 fp32 -> bf16 hi/lo pairs
__device__ __forceinline__ void cvt8(const float* f, __nv_bfloat16* sh, __nv_bfloat16* sl)
{
#pragma unroll
    for (int j = 0; j < 4; j++) {
        const float x0 = f[2*j], x1 = f[2*j+1];
        const __nv_bfloat16 h0 = __float2bfloat16_rn(x0);
        const __nv_bfloat16 h1 = __float2bfloat16_rn(x1);
        ((__nv_bfloat162*)sh)[j] = __halves2bfloat162(h0, h1);
        ((__nv_bfloat162*)sl)[j] = __halves2bfloat162(
            __float2bfloat16_rn(x0 - __bfloat162float(h0)),
            __float2bfloat16_rn(x1 - __bfloat162float(h1)));
    }
}

// ---------------------------------------------------------------------------
// Unified wmma GEMM: block 128x128, BK=16, 8 warps (2m x 4n), warp tile 64x32.
//   sel 0..3: Y = branch buffer, A = gather from X via (s1,s2,s3,st)
//   sel 4   : Y = outF (contiguous), A = h*a0+w*a1+d*a2+c*a3 (fused combine)
// Double-buffered static smem: 2 stages x 20992 B = 41984 B.
// ---------------------------------------------------------------------------
#define KPAD2 24                 // A smem row stride (16 data + 8 pad), bf16
#define NPAD 136                 // B smem row stride (128 data + 8 pad), bf16
#define A_ELE (128 * KPAD2)      // 3072 bf16
#define B_ELE (16 * NPAD)        // 2176 bf16
#define STG_ELE (2 * A_ELE + 2 * B_ELE)   // 10496 bf16 = 20992 B
#define OFF_AL A_ELE
#define OFF_BH (2 * A_ELE)
#define OFF_BL (2 * A_ELE + B_ELE)
#define EPAD 36                  // f32 epilogue row stride

__global__ __launch_bounds__(256)
void gemm_wmma(const float* __restrict__ X, const float* __restrict__ Wm,
               const float* __restrict__ bias, int sel,
               int s1, int s2, int s3, int st, float* __restrict__ outF)
{
    __shared__ __align__(256) __nv_bfloat16 smem[2 * STG_ELE];   // 41984 B

    const int tid = threadIdx.x;
    const int wid = tid >> 5;
    const int lane = tid & 31;
    const int bm = blockIdx.y * 128;
    const int bn = blockIdx.x * 128;
    float* Y = (sel == 0) ? g_h : (sel == 1) ? g_w : (sel == 2) ? g_d
             : (sel == 3) ? g_c : outF;

    // ---- A loader: thread -> (row r = tid>>1, k-oct lk = (tid&1)*8) ----
    const int r  = tid >> 1;
    const int lk = (tid & 1) * 8;
    const int abase = row_base(bm + r, s1, s2, s3) + lk;   // branch gather base
    const int cbase = (bm + r) * 1024 + lk;                // contiguous (final)
    const int awbase = ((bm >> 12) << 10) + lk;            // g_a row for batch
    const int sA = r * KPAD2 + lk;

    // ---- B loader: thread -> (krow = tid>>4, ncol = (tid&15)*8) ----
    const int krow = tid >> 4;                             // 0..15
    const int ncol = (tid & 15) * 8;
    const int bbase = krow * 1024 + bn + ncol;
    const int sB = krow * NPAD + ncol;

    float fa[8], fb[8];

// chunk t covers k in [t*16, t*16+16): A offset (t>>2)*st + (t&3)*16
#define GLOADA(T) do {                                                         \
    if (sel < 4) {                                                             \
        const float4* p_ = (const float4*)(X + abase + ((T) >> 2) * st + ((T) & 3) * 16); \
        float4 v0_ = p_[0], v1_ = p_[1];                                       \
        fa[0]=v0_.x; fa[1]=v0_.y; fa[2]=v0_.z; fa[3]=v0_.w;                    \
        fa[4]=v1_.x; fa[5]=v1_.y; fa[6]=v1_.z; fa[7]=v1_.w;                    \
    } else {                                                                   \
        const int i0_ = cbase + (T) * 16;                                      \
        const int aw_ = awbase + (T) * 16;                                     \
        _Pragma("unroll")                                                      \
        for (int q_ = 0; q_ < 2; q_++) {                                       \
            float4 h_ = *(const float4*)(g_h + i0_ + 4*q_);                    \
            float4 w_ = *(const float4*)(g_w + i0_ + 4*q_);                    \
            float4 d_ = *(const float4*)(g_d + i0_ + 4*q_);                    \
            float4 c_ = *(const float4*)(g_c + i0_ + 4*q_);                    \
            float4 a0_ = *(const float4*)(g_a + 0*8192 + aw_ + 4*q_);          \
            float4 a1_ = *(const float4*)(g_a + 1*8192 + aw_ + 4*q_);          \
            float4 a2_ = *(const float4*)(g_a + 2*8192 + aw_ + 4*q_);          \
            float4 a3_ = *(const float4*)(g_a + 3*8192 + aw_ + 4*q_);          \
            fa[4*q_+0] = h_.x*a0_.x + w_.x*a1_.x + d_.x*a2_.x + c_.x*a3_.x;    \
            fa[4*q_+1] = h_.y*a0_.y + w_.y*a1_.y + d_.y*a2_.y + c_.y*a3_.y;    \
            fa[4*q_+2] = h_.z*a0_.z + w_.z*a1_.z + d_.z*a2_.z + c_.z*a3_.z;    \
            fa[4*q_+3] = h_.w*a0_.w + w_.w*a1_.w + d_.w*a2_.w + c_.w*a3_.w;    \
        }                                                                      \
    }                                                                          \
} while (0)

#define GLOADB(T) do {                                                         \
    const float4* p_ = (const float4*)(Wm + bbase + (T) * 16 * 1024);          \
    float4 v0_ = p_[0], v1_ = p_[1];                                           \
    fb[0]=v0_.x; fb[1]=v0_.y; fb[2]=v0_.z; fb[3]=v0_.w;                        \
    fb[4]=v1_.x; fb[5]=v1_.y; fb[6]=v1_.z; fb[7]=v1_.w;                        \
} while (0)

#define SCVT(STG) do {                                                         \
    __nv_bfloat16* s0_ = smem + (STG) * STG_ELE;                               \
    cvt8(fa, s0_ + sA, s0_ + OFF_AL + sA);                                     \
    cvt8(fb, s0_ + OFF_BH + sB, s0_ + OFF_BL + sB);                            \
} while (0)

    // ---- warp tiling: 2(m) x 4(n); warp tile 64x32 = 4x2 wmma frags ----
    const int wm = (wid >> 2) * 64;
    const int wn = (wid & 3) * 32;

    wmma::fragment<wmma::accumulator, 16, 16, 16, float> acc[4][2];
#pragma unroll
    for (int mt = 0; mt < 4; mt++)
#pragma unroll
        for (int nt = 0; nt < 2; nt++)
            wmma::fill_fragment(acc[mt][nt], 0.0f);

    GLOADA(0);
    GLOADB(0);
    SCVT(0);
    __syncthreads();

#pragma unroll 2
    for (int t = 0; t < 64; t++) {
        if (t < 63) { GLOADA(t + 1); GLOADB(t + 1); }   // prefetch (hidden by MMAs)

        {   // compute on stage t&1
            const __nv_bfloat16* s0 = smem + (t & 1) * STG_ELE;
            wmma::fragment<wmma::matrix_a, 16, 16, 16, __nv_bfloat16, wmma::row_major> fah[4], fal[4];
            wmma::fragment<wmma::matrix_b, 16, 16, 16, __nv_bfloat16, wmma::row_major> fbh[2], fbl[2];
#pragma unroll
            for (int mt = 0; mt < 4; mt++) {
                wmma::load_matrix_sync(fah[mt], s0 + (wm + mt*16) * KPAD2, KPAD2);
                wmma::load_matrix_sync(fal[mt], s0 + OFF_AL + (wm + mt*16) * KPAD2, KPAD2);
            }
#pragma unroll
            for (int nt = 0; nt < 2; nt++) {
                wmma::load_matrix_sync(fbh[nt], s0 + OFF_BH + wn + nt*16, NPAD);
                wmma::load_matrix_sync(fbl[nt], s0 + OFF_BL + wn + nt*16, NPAD);
            }
#pragma unroll
            for (int mt = 0; mt < 4; mt++)
#pragma unroll
                for (int nt = 0; nt < 2; nt++) {
                    wmma::mma_sync(acc[mt][nt], fah[mt], fbh[nt], acc[mt][nt]);
                    wmma::mma_sync(acc[mt][nt], fah[mt], fbl[nt], acc[mt][nt]);
                    wmma::mma_sync(acc[mt][nt], fal[mt], fbh[nt], acc[mt][nt]);
                }
        }

        if (t < 63) SCVT((t + 1) & 1);   // fill other stage (overlaps MMA drain)
        __syncthreads();
    }

    // ---- epilogue: per-warp smem staging (reuse operand smem), scatter ----
    float* ep = (float*)smem + wid * (16 * EPAD);   // 8 * 2304B = 18432B

    const int n0  = bn + wn;                 // multiple of 32
    const int cc  = (lane & 7) * 4;          // 0..28
    const int offn = (n0 >> 6) * st + (n0 & 63) + cc;
    const int offc = n0 + cc;                // contiguous (final)
    const float4 bv = *(const float4*)(bias + n0 + cc);

#pragma unroll
    for (int mt = 0; mt < 4; mt++) {
#pragma unroll
        for (int nt = 0; nt < 2; nt++)
            wmma::store_matrix_sync(ep + nt*16, acc[mt][nt], EPAD, wmma::mem_row_major);
        __syncwarp();
#pragma unroll
        for (int i = 0; i < 4; i++) {
            const int rr = i * 4 + (lane >> 3);           // 0..15
            const int m = bm + wm + mt * 16 + rr;
            const float* s = ep + rr * EPAD + cc;
            float4 o;
            o.x = s[0] + bv.x; o.y = s[1] + bv.y;
            o.z = s[2] + bv.z; o.w = s[3] + bv.w;
            const int adr = (sel < 4) ? (row_base(m, s1, s2, s3) + offn)
                                      : (m * 1024 + offc);
            *(float4*)(Y + adr) = o;
        }
        __syncwarp();
    }
#undef GLOADA
#undef GLOADB
#undef SCVT
}

// ---------------------------------------------------------------------------
// mean over positions (deterministic 2-stage)
// ---------------------------------------------------------------------------
__global__ void reduce1()
{
    const int b = blockIdx.x, pc = blockIdx.y, ch = threadIdx.x;
    const int base = b * 4194304 + pc * 131072 + ch;
    float s = 0.0f;
#pragma unroll 4
    for (int p = 0; p < 128; p++) {
        const int idx = base + p * 1024;
        s += g_h[idx] + g_w[idx] + g_d[idx] + g_c[idx];
    }
    g_partial[(b * 32 + pc) * 1024 + ch] = s;
}
__global__ void reduce2()
{
    const int b = blockIdx.x, ch = threadIdx.x;
    float s = 0.0f;
#pragma unroll
    for (int pc = 0; pc < 32; pc++) s += g_partial[(b * 32 + pc) * 1024 + ch];
    g_sum[b * 1024 + ch] = s;
}

// ---------------------------------------------------------------------------
// Gating MLP + softmax (tiny)
// ---------------------------------------------------------------------------
__global__ __launch_bounds__(256)
void mlp_kernel(const float* __restrict__ w1, const float* __restrict__ b1,
                const float* __restrict__ w2, const float* __restrict__ b2)
{
    __shared__ float sv[1024];
    __shared__ float tt[256];
    __shared__ float zs[4096];
    const int b = blockIdx.x, tid = threadIdx.x;

    for (int c = tid; c < 1024; c += 256)
        sv[c] = g_sum[b * 1024 + c] * (1.0f / 4096.0f);
    __syncthreads();
    {
        float acc = b1[tid];
        for (int k = 0; k < 1024; k++) acc += sv[k] * w1[k * 256 + tid];
        tt[tid] = 0.5f * acc * (1.0f + erff(acc * 0.7071067811865476f));
    }
    __syncthreads();
    for (int n = tid; n < 4096; n += 256) {
        float acc = b2[n];
#pragma unroll 8
        for (int k = 0; k < 256; k++) acc += tt[k] * w2[k * 4096 + n];
        zs[n] = acc;
    }
    __syncthreads();
    for (int c = tid; c < 1024; c += 256) {
        const float v0 = zs[4*c+0], v1 = zs[4*c+1], v2 = zs[4*c+2], v3 = zs[4*c+3];
        const float mx = fmaxf(fmaxf(v0, v1), fmaxf(v2, v3));
        const float e0 = expf(v0-mx), e1 = expf(v1-mx), e2 = expf(v2-mx), e3 = expf(v3-mx);
        const float inv = 1.0f / (e0 + e1 + e2 + e3);
        g_a[0*8192 + b*1024 + c] = e0 * inv;
        g_a[1*8192 + b*1024 + c] = e1 * inv;
        g_a[2*8192 + b*1024 + c] = e2 * inv;
        g_a[3*8192 + b*1024 + c] = e3 * inv;
    }
}

// ---------------------------------------------------------------------------
extern "C" void kernel_launch(void* const* d_in, const int* in_sizes, int n_in,
                              void* d_out, int out_size)
{
    const float* x  = (const float*)d_in[0];
    const float* wh = (const float*)d_in[1];
    const float* bh = (const float*)d_in[2];
    const float* ww = (const float*)d_in[3];
    const float* bw = (const float*)d_in[4];
    const float* wd = (const float*)d_in[5];
    const float* bd = (const float*)d_in[6];
    const float* wc = (const float*)d_in[7];
    const float* bc = (const float*)d_in[8];
    const float* w1 = (const float*)d_in[9];
    const float* b1 = (const float*)d_in[10];
    const float* w2 = (const float*)d_in[11];
    const float* b2 = (const float*)d_in[12];
    const float* wp = (const float*)d_in[13];
    const float* bp = (const float*)d_in[14];
    float* out = (float*)d_out;

    dim3 grid(8, 256);

    // branch GEMMs: h, w, d, c
    gemm_wmma<<<grid, 256>>>(x, wh, bh, 0, 64,     16384, 1024, 262144, nullptr);
    gemm_wmma<<<grid, 256>>>(x, ww, bw, 1, 262144, 64,    1024, 16384,  nullptr);
    gemm_wmma<<<grid, 256>>>(x, wd, bd, 2, 262144, 16384, 64,   1024,   nullptr);
    gemm_wmma<<<grid, 256>>>(x, wc, bc, 3, 262144, 16384, 1024, 64,     nullptr);

    // mean + gating
    reduce1<<<dim3(8, 32), 1024>>>();
    reduce2<<<8, 1024>>>();
    mlp_kernel<<<8, 256>>>(w1, b1, w2, b2);

    // final projection with fused weighted combine
    gemm_wmma<<<grid, 256>>>(x, wp, bp, 4, 262144, 16384, 1024, 64, out);
}

// round 10
// speedup vs baseline: 1.3122x; 1.3122x over previous
#include <cuda_runtime.h>
#include <cuda_bf16.h>
#include <mma.h>
#include <cstdint>
#include <math.h>

using namespace nvcuda;

// ===========================================================================
// WeightedPermuteMLP — split-bf16 wmma, double-buffered smem (BK=16),
// 2 CTAs/SM via __launch_bounds__(256, 2).
// B=8, SEG=16, DIM=1024, HID=256.  5 GEMMs M=32768, N=K=1024.
// fp32 loads (proven addressing) -> register split bf16 hi/lo -> smem -> wmma.
// D = Ah*Bh + Ah*Bl + Al*Bh (fp32 accum), rel_err ~1e-5.
// ===========================================================================

#define NELEM 33554432

__device__ __align__(256) float g_h[NELEM];
__device__ __align__(256) float g_w[NELEM];
__device__ __align__(256) float g_d[NELEM];
__device__ __align__(256) float g_c[NELEM];
__device__ __align__(256) float g_partial[8 * 32 * 1024];
__device__ __align__(256) float g_sum[8 * 1024];
__device__ __align__(256) float g_a[4 * 8 * 1024];   // [q][b][chan]

__device__ __forceinline__ int row_base(int m, int s1, int s2, int s3) {
    return (m >> 12) * 4194304 + ((m >> 8) & 15) * s1 + ((m >> 4) & 15) * s2 + (m & 15) * s3;
}

// split 8 fp32 -> bf16 hi/lo pairs
__device__ __forceinline__ void cvt8(const float* f, __nv_bfloat16* sh, __nv_bfloat16* sl)
{
#pragma unroll
    for (int j = 0; j < 4; j++) {
        const float x0 = f[2*j], x1 = f[2*j+1];
        const __nv_bfloat16 h0 = __float2bfloat16_rn(x0);
        const __nv_bfloat16 h1 = __float2bfloat16_rn(x1);
        ((__nv_bfloat162*)sh)[j] = __halves2bfloat162(h0, h1);
        ((__nv_bfloat162*)sl)[j] = __halves2bfloat162(
            __float2bfloat16_rn(x0 - __bfloat162float(h0)),
            __float2bfloat16_rn(x1 - __bfloat162float(h1)));
    }
}

// ---------------------------------------------------------------------------
// Unified wmma GEMM: block 128x128, BK=16, 8 warps (2m x 4n), warp tile 64x32.
//   sel 0..3: Y = branch buffer, A = gather from X via (s1,s2,s3,st)
//   sel 4   : Y = outF (contiguous), A = h*a0+w*a1+d*a2+c*a3 (fused combine)
// Double-buffered static smem: 2 stages x 20992 B = 41984 B; 2 CTAs/SM.
// ---------------------------------------------------------------------------
#define KPAD2 24                 // A smem row stride (16 data + 8 pad), bf16
#define NPAD 136                 // B smem row stride (128 data + 8 pad), bf16
#define A_ELE (128 * KPAD2)      // 3072 bf16
#define B_ELE (16 * NPAD)        // 2176 bf16
#define STG_ELE (2 * A_ELE + 2 * B_ELE)   // 10496 bf16 = 20992 B
#define OFF_AL A_ELE
#define OFF_BH (2 * A_ELE)
#define OFF_BL (2 * A_ELE + B_ELE)
#define EPAD 36                  // f32 epilogue row stride

__global__ __launch_bounds__(256, 2)
void gemm_wmma(const float* __restrict__ X, const float* __restrict__ Wm,
               const float* __restrict__ bias, int sel,
               int s1, int s2, int s3, int st, float* __restrict__ outF)
{
    __shared__ __align__(256) __nv_bfloat16 smem[2 * STG_ELE];   // 41984 B

    const int tid = threadIdx.x;
    const int wid = tid >> 5;
    const int lane = tid & 31;
    const int bm = blockIdx.y * 128;
    const int bn = blockIdx.x * 128;
    float* Y = (sel == 0) ? g_h : (sel == 1) ? g_w : (sel == 2) ? g_d
             : (sel == 3) ? g_c : outF;

    // ---- A loader: thread -> (row r = tid>>1, k-oct lk = (tid&1)*8) ----
    const int r  = tid >> 1;
    const int lk = (tid & 1) * 8;
    const int abase = row_base(bm + r, s1, s2, s3) + lk;   // branch gather base
    const int cbase = (bm + r) * 1024 + lk;                // contiguous (final)
    const int awbase = ((bm >> 12) << 10) + lk;            // g_a row for batch
    const int sA = r * KPAD2 + lk;

    // ---- B loader: thread -> (krow = tid>>4, ncol = (tid&15)*8) ----
    const int krow = tid >> 4;                             // 0..15
    const int ncol = (tid & 15) * 8;
    const int bbase = krow * 1024 + bn + ncol;
    const int sB = krow * NPAD + ncol;

    float fa[8], fb[8];

// chunk t covers k in [t*16, t*16+16): A offset (t>>2)*st + (t&3)*16
#define GLOADA(T) do {                                                         \
    if (sel < 4) {                                                             \
        const float4* p_ = (const float4*)(X + abase + ((T) >> 2) * st + ((T) & 3) * 16); \
        float4 v0_ = p_[0], v1_ = p_[1];                                       \
        fa[0]=v0_.x; fa[1]=v0_.y; fa[2]=v0_.z; fa[3]=v0_.w;                    \
        fa[4]=v1_.x; fa[5]=v1_.y; fa[6]=v1_.z; fa[7]=v1_.w;                    \
    } else {                                                                   \
        const int i0_ = cbase + (T) * 16;                                      \
        const int aw_ = awbase + (T) * 16;                                     \
        _Pragma("unroll")                                                      \
        for (int q_ = 0; q_ < 2; q_++) {                                       \
            float4 h_ = *(const float4*)(g_h + i0_ + 4*q_);                    \
            float4 w_ = *(const float4*)(g_w + i0_ + 4*q_);                    \
            float4 d_ = *(const float4*)(g_d + i0_ + 4*q_);                    \
            float4 c_ = *(const float4*)(g_c + i0_ + 4*q_);                    \
            float4 a0_ = *(const float4*)(g_a + 0*8192 + aw_ + 4*q_);          \
            float4 a1_ = *(const float4*)(g_a + 1*8192 + aw_ + 4*q_);          \
            float4 a2_ = *(const float4*)(g_a + 2*8192 + aw_ + 4*q_);          \
            float4 a3_ = *(const float4*)(g_a + 3*8192 + aw_ + 4*q_);          \
            fa[4*q_+0] = h_.x*a0_.x + w_.x*a1_.x + d_.x*a2_.x + c_.x*a3_.x;    \
            fa[4*q_+1] = h_.y*a0_.y + w_.y*a1_.y + d_.y*a2_.y + c_.y*a3_.y;    \
            fa[4*q_+2] = h_.z*a0_.z + w_.z*a1_.z + d_.z*a2_.z + c_.z*a3_.z;    \
            fa[4*q_+3] = h_.w*a0_.w + w_.w*a1_.w + d_.w*a2_.w + c_.w*a3_.w;    \
        }                                                                      \
    }                                                                          \
} while (0)

#define GLOADB(T) do {                                                         \
    const float4* p_ = (const float4*)(Wm + bbase + (T) * 16 * 1024);          \
    float4 v0_ = p_[0], v1_ = p_[1];                                           \
    fb[0]=v0_.x; fb[1]=v0_.y; fb[2]=v0_.z; fb[3]=v0_.w;                        \
    fb[4]=v1_.x; fb[5]=v1_.y; fb[6]=v1_.z; fb[7]=v1_.w;                        \
} while (0)

#define SCVT(STG) do {                                                         \
    __nv_bfloat16* s0_ = smem + (STG) * STG_ELE;                               \
    cvt8(fa, s0_ + sA, s0_ + OFF_AL + sA);                                     \
    cvt8(fb, s0_ + OFF_BH + sB, s0_ + OFF_BL + sB);                            \
} while (0)

    // ---- warp tiling: 2(m) x 4(n); warp tile 64x32 = 4x2 wmma frags ----
    const int wm = (wid >> 2) * 64;
    const int wn = (wid & 3) * 32;

    wmma::fragment<wmma::accumulator, 16, 16, 16, float> acc[4][2];
#pragma unroll
    for (int mt = 0; mt < 4; mt++)
#pragma unroll
        for (int nt = 0; nt < 2; nt++)
            wmma::fill_fragment(acc[mt][nt], 0.0f);

    GLOADA(0);
    GLOADB(0);
    SCVT(0);
    __syncthreads();

    for (int t = 0; t < 64; t++) {
        if (t < 63) { GLOADA(t + 1); GLOADB(t + 1); }   // prefetch (hidden by MMAs)

        {   // compute on stage t&1
            const __nv_bfloat16* s0 = smem + (t & 1) * STG_ELE;
            wmma::fragment<wmma::matrix_a, 16, 16, 16, __nv_bfloat16, wmma::row_major> fah[4], fal[4];
            wmma::fragment<wmma::matrix_b, 16, 16, 16, __nv_bfloat16, wmma::row_major> fbh[2], fbl[2];
#pragma unroll
            for (int mt = 0; mt < 4; mt++) {
                wmma::load_matrix_sync(fah[mt], s0 + (wm + mt*16) * KPAD2, KPAD2);
                wmma::load_matrix_sync(fal[mt], s0 + OFF_AL + (wm + mt*16) * KPAD2, KPAD2);
            }
#pragma unroll
            for (int nt = 0; nt < 2; nt++) {
                wmma::load_matrix_sync(fbh[nt], s0 + OFF_BH + wn + nt*16, NPAD);
                wmma::load_matrix_sync(fbl[nt], s0 + OFF_BL + wn + nt*16, NPAD);
            }
#pragma unroll
            for (int mt = 0; mt < 4; mt++)
#pragma unroll
                for (int nt = 0; nt < 2; nt++) {
                    wmma::mma_sync(acc[mt][nt], fah[mt], fbh[nt], acc[mt][nt]);
                    wmma::mma_sync(acc[mt][nt], fah[mt], fbl[nt], acc[mt][nt]);
                    wmma::mma_sync(acc[mt][nt], fal[mt], fbh[nt], acc[mt][nt]);
                }
        }

        if (t < 63) SCVT((t + 1) & 1);   // fill other stage (overlaps MMA drain)
        __syncthreads();
    }

    // ---- epilogue: per-warp smem staging (reuse operand smem), scatter ----
    float* ep = (float*)smem + wid * (16 * EPAD);   // 8 * 2304B = 18432B

    const int n0  = bn + wn;                 // multiple of 32
    const int cc  = (lane & 7) * 4;          // 0..28
    const int offn = (n0 >> 6) * st + (n0 & 63) + cc;
    const int offc = n0 + cc;                // contiguous (final)
    const float4 bv = *(const float4*)(bias + n0 + cc);

#pragma unroll
    for (int mt = 0; mt < 4; mt++) {
#pragma unroll
        for (int nt = 0; nt < 2; nt++)
            wmma::store_matrix_sync(ep + nt*16, acc[mt][nt], EPAD, wmma::mem_row_major);
        __syncwarp();
#pragma unroll
        for (int i = 0; i < 4; i++) {
            const int rr = i * 4 + (lane >> 3);           // 0..15
            const int m = bm + wm + mt * 16 + rr;
            const float* s = ep + rr * EPAD + cc;
            float4 o;
            o.x = s[0] + bv.x; o.y = s[1] + bv.y;
            o.z = s[2] + bv.z; o.w = s[3] + bv.w;
            const int adr = (sel < 4) ? (row_base(m, s1, s2, s3) + offn)
                                      : (m * 1024 + offc);
            *(float4*)(Y + adr) = o;
        }
        __syncwarp();
    }
#undef GLOADA
#undef GLOADB
#undef SCVT
}

// ---------------------------------------------------------------------------
// mean over positions (deterministic 2-stage)
// ---------------------------------------------------------------------------
__global__ void reduce1()
{
    const int b = blockIdx.x, pc = blockIdx.y, ch = threadIdx.x;
    const int base = b * 4194304 + pc * 131072 + ch;
    float s = 0.0f;
#pragma unroll 4
    for (int p = 0; p < 128; p++) {
        const int idx = base + p * 1024;
        s += g_h[idx] + g_w[idx] + g_d[idx] + g_c[idx];
    }
    g_partial[(b * 32 + pc) * 1024 + ch] = s;
}
__global__ void reduce2()
{
    const int b = blockIdx.x, ch = threadIdx.x;
    float s = 0.0f;
#pragma unroll
    for (int pc = 0; pc < 32; pc++) s += g_partial[(b * 32 + pc) * 1024 + ch];
    g_sum[b * 1024 + ch] = s;
}

// ---------------------------------------------------------------------------
// Gating MLP + softmax (tiny)
// ---------------------------------------------------------------------------
__global__ __launch_bounds__(256)
void mlp_kernel(const float* __restrict__ w1, const float* __restrict__ b1,
                const float* __restrict__ w2, const float* __restrict__ b2)
{
    __shared__ float sv[1024];
    __shared__ float tt[256];
    __shared__ float zs[4096];
    const int b = blockIdx.x, tid = threadIdx.x;

    for (int c = tid; c < 1024; c += 256)
        sv[c] = g_sum[b * 1024 + c] * (1.0f / 4096.0f);
    __syncthreads();
    {
        float acc = b1[tid];
        for (int k = 0; k < 1024; k++) acc += sv[k] * w1[k * 256 + tid];
        tt[tid] = 0.5f * acc * (1.0f + erff(acc * 0.7071067811865476f));
    }
    __syncthreads();
    for (int n = tid; n < 4096; n += 256) {
        float acc = b2[n];
#pragma unroll 8
        for (int k = 0; k < 256; k++) acc += tt[k] * w2[k * 4096 + n];
        zs[n] = acc;
    }
    __syncthreads();
    for (int c = tid; c < 1024; c += 256) {
        const float v0 = zs[4*c+0], v1 = zs[4*c+1], v2 = zs[4*c+2], v3 = zs[4*c+3];
        const float mx = fmaxf(fmaxf(v0, v1), fmaxf(v2, v3));
        const float e0 = expf(v0-mx), e1 = expf(v1-mx), e2 = expf(v2-mx), e3 = expf(v3-mx);
        const float inv = 1.0f / (e0 + e1 + e2 + e3);
        g_a[0*8192 + b*1024 + c] = e0 * inv;
        g_a[1*8192 + b*1024 + c] = e1 * inv;
        g_a[2*8192 + b*1024 + c] = e2 * inv;
        g_a[3*8192 + b*1024 + c] = e3 * inv;
    }
}

// ---------------------------------------------------------------------------
extern "C" void kernel_launch(void* const* d_in, const int* in_sizes, int n_in,
                              void* d_out, int out_size)
{
    const float* x  = (const float*)d_in[0];
    const float* wh = (const float*)d_in[1];
    const float* bh = (const float*)d_in[2];
    const float* ww = (const float*)d_in[3];
    const float* bw = (const float*)d_in[4];
    const float* wd = (const float*)d_in[5];
    const float* bd = (const float*)d_in[6];
    const float* wc = (const float*)d_in[7];
    const float* bc = (const float*)d_in[8];
    const float* w1 = (const float*)d_in[9];
    const float* b1 = (const float*)d_in[10];
    const float* w2 = (const float*)d_in[11];
    const float* b2 = (const float*)d_in[12];
    const float* wp = (const float*)d_in[13];
    const float* bp = (const float*)d_in[14];
    float* out = (float*)d_out;

    dim3 grid(8, 256);

    // branch GEMMs: h, w, d, c
    gemm_wmma<<<grid, 256>>>(x, wh, bh, 0, 64,     16384, 1024, 262144, nullptr);
    gemm_wmma<<<grid, 256>>>(x, ww, bw, 1, 262144, 64,    1024, 16384,  nullptr);
    gemm_wmma<<<grid, 256>>>(x, wd, bd, 2, 262144, 16384, 64,   1024,   nullptr);
    gemm_wmma<<<grid, 256>>>(x, wc, bc, 3, 262144, 16384, 1024, 64,     nullptr);

    // mean + gating
    reduce1<<<dim3(8, 32), 1024>>>();
    reduce2<<<8, 1024>>>();
    mlp_kernel<<<8, 256>>>(w1, b1, w2, b2);

    // final projection with fused weighted combine
    gemm_wmma<<<grid, 256>>>(x, wp, bp, 4, 262144, 16384, 1024, 64, out);
}

// round 11
// speedup vs baseline: 1.6950x; 1.2917x over previous
#include <cuda_runtime.h>
#include <cuda_bf16.h>
#include <cstdint>
#include <math.h>

// ===========================================================================
// WeightedPermuteMLP — split-bf16, manual ldmatrix + mma.sync.m16n8k16.
// B=8, SEG=16, DIM=1024, HID=256.  5 GEMMs M=32768, N=K=1024.
// fp32 loads (proven addressing) -> register split bf16 hi/lo -> smem
// -> ldmatrix.x4 (A) / ldmatrix.x4.trans (B) -> mma.sync (3 products).
// D = Ah*Bh + Ah*Bl + Al*Bh (fp32 accum), rel_err ~1e-5.
// Double-buffered smem (BK=16), 2 CTAs/SM.
// ===========================================================================

#define NELEM 33554432

__device__ __align__(256) float g_h[NELEM];
__device__ __align__(256) float g_w[NELEM];
__device__ __align__(256) float g_d[NELEM];
__device__ __align__(256) float g_c[NELEM];
__device__ __align__(256) float g_partial[8 * 32 * 1024];
__device__ __align__(256) float g_sum[8 * 1024];
__device__ __align__(256) float g_a[4 * 8 * 1024];   // [q][b][chan]

__device__ __forceinline__ int row_base(int m, int s1, int s2, int s3) {
    return (m >> 12) * 4194304 + ((m >> 8) & 15) * s1 + ((m >> 4) & 15) * s2 + (m & 15) * s3;
}

__device__ __forceinline__ uint32_t s2u(const void* p) {
    uint32_t a;
    asm("{ .reg .u64 t; cvta.to.shared.u64 t, %1; cvt.u32.u64 %0, t; }" : "=r"(a) : "l"(p));
    return a;
}

// split 8 fp32 -> bf16 hi/lo pairs
__device__ __forceinline__ void cvt8(const float* f, __nv_bfloat16* sh, __nv_bfloat16* sl)
{
#pragma unroll
    for (int j = 0; j < 4; j++) {
        const float x0 = f[2*j], x1 = f[2*j+1];
        const __nv_bfloat16 h0 = __float2bfloat16_rn(x0);
        const __nv_bfloat16 h1 = __float2bfloat16_rn(x1);
        ((__nv_bfloat162*)sh)[j] = __halves2bfloat162(h0, h1);
        ((__nv_bfloat162*)sl)[j] = __halves2bfloat162(
            __float2bfloat16_rn(x0 - __bfloat162float(h0)),
            __float2bfloat16_rn(x1 - __bfloat162float(h1)));
    }
}

#define LDSM4(R, ADDR) \
    asm volatile("ldmatrix.sync.aligned.m8n8.x4.shared.b16 {%0,%1,%2,%3}, [%4];" \
                 : "=r"((R)[0]), "=r"((R)[1]), "=r"((R)[2]), "=r"((R)[3]) : "r"(ADDR))
#define LDSM4T(R, ADDR) \
    asm volatile("ldmatrix.sync.aligned.m8n8.x4.trans.shared.b16 {%0,%1,%2,%3}, [%4];" \
                 : "=r"((R)[0]), "=r"((R)[1]), "=r"((R)[2]), "=r"((R)[3]) : "r"(ADDR))
#define MMA16816(D, A, B0, B1) \
    asm volatile("mma.sync.aligned.m16n8k16.row.col.f32.bf16.bf16.f32 " \
                 "{%0,%1,%2,%3}, {%4,%5,%6,%7}, {%8,%9}, {%0,%1,%2,%3};" \
                 : "+f"((D)[0]), "+f"((D)[1]), "+f"((D)[2]), "+f"((D)[3]) \
                 : "r"((A)[0]), "r"((A)[1]), "r"((A)[2]), "r"((A)[3]), "r"(B0), "r"(B1))

// ---------------------------------------------------------------------------
// Unified GEMM: block 128x128, BK=16, 8 warps (2m x 4n), warp tile 64x32.
//   sel 0..3: Y = branch buffer, A = gather from X via (s1,s2,s3,st)
//   sel 4   : Y = outF (contiguous), A = h*a0+w*a1+d*a2+c*a3 (fused combine)
// Double-buffered static smem: 2 stages x 20992 B = 41984 B; 2 CTAs/SM.
// ---------------------------------------------------------------------------
#define KPAD2 24                 // A smem row stride (16 data + 8 pad), bf16
#define NPAD 136                 // B smem row stride (128 data + 8 pad), bf16
#define A_ELE (128 * KPAD2)      // 3072 bf16
#define B_ELE (16 * NPAD)        // 2176 bf16
#define STG_ELE (2 * A_ELE + 2 * B_ELE)   // 10496 bf16 = 20992 B
#define STG_BYTES (STG_ELE * 2)
#define OFF_AL A_ELE
#define OFF_BH (2 * A_ELE)
#define OFF_BL (2 * A_ELE + B_ELE)
#define EPAD 36                  // f32 epilogue row stride

__global__ __launch_bounds__(256, 2)
void gemm_mma(const float* __restrict__ X, const float* __restrict__ Wm,
              const float* __restrict__ bias, int sel,
              int s1, int s2, int s3, int st, float* __restrict__ outF)
{
    __shared__ __align__(256) __nv_bfloat16 smem[2 * STG_ELE];   // 41984 B

    const int tid = threadIdx.x;
    const int wid = tid >> 5;
    const int lane = tid & 31;
    const int bm = blockIdx.y * 128;
    const int bn = blockIdx.x * 128;
    float* Y = (sel == 0) ? g_h : (sel == 1) ? g_w : (sel == 2) ? g_d
             : (sel == 3) ? g_c : outF;

    // ---- A loader: thread -> (row r = tid>>1, k-oct lk = (tid&1)*8) ----
    const int r  = tid >> 1;
    const int lk = (tid & 1) * 8;
    const int abase = row_base(bm + r, s1, s2, s3) + lk;
    const int cbase = (bm + r) * 1024 + lk;
    const int awbase = ((bm >> 12) << 10) + lk;
    const int sA = r * KPAD2 + lk;

    // ---- B loader: thread -> (krow = tid>>4, ncol = (tid&15)*8) ----
    const int krow = tid >> 4;
    const int ncol = (tid & 15) * 8;
    const int bbase = krow * 1024 + bn + ncol;
    const int sB = krow * NPAD + ncol;

    float fa[8], fb[8];

#define GLOADA(T) do {                                                         \
    if (sel < 4) {                                                             \
        const float4* p_ = (const float4*)(X + abase + ((T) >> 2) * st + ((T) & 3) * 16); \
        float4 v0_ = p_[0], v1_ = p_[1];                                       \
        fa[0]=v0_.x; fa[1]=v0_.y; fa[2]=v0_.z; fa[3]=v0_.w;                    \
        fa[4]=v1_.x; fa[5]=v1_.y; fa[6]=v1_.z; fa[7]=v1_.w;                    \
    } else {                                                                   \
        const int i0_ = cbase + (T) * 16;                                      \
        const int aw_ = awbase + (T) * 16;                                     \
        _Pragma("unroll")                                                      \
        for (int q_ = 0; q_ < 2; q_++) {                                       \
            float4 h_ = *(const float4*)(g_h + i0_ + 4*q_);                    \
            float4 w_ = *(const float4*)(g_w + i0_ + 4*q_);                    \
            float4 d_ = *(const float4*)(g_d + i0_ + 4*q_);                    \
            float4 c_ = *(const float4*)(g_c + i0_ + 4*q_);                    \
            float4 a0_ = *(const float4*)(g_a + 0*8192 + aw_ + 4*q_);          \
            float4 a1_ = *(const float4*)(g_a + 1*8192 + aw_ + 4*q_);          \
            float4 a2_ = *(const float4*)(g_a + 2*8192 + aw_ + 4*q_);          \
            float4 a3_ = *(const float4*)(g_a + 3*8192 + aw_ + 4*q_);          \
            fa[4*q_+0] = h_.x*a0_.x + w_.x*a1_.x + d_.x*a2_.x + c_.x*a3_.x;    \
            fa[4*q_+1] = h_.y*a0_.y + w_.y*a1_.y + d_.y*a2_.y + c_.y*a3_.y;    \
            fa[4*q_+2] = h_.z*a0_.z + w_.z*a1_.z + d_.z*a2_.z + c_.z*a3_.z;    \
            fa[4*q_+3] = h_.w*a0_.w + w_.w*a1_.w + d_.w*a2_.w + c_.w*a3_.w;    \
        }                                                                      \
    }                                                                          \
} while (0)

#define GLOADB(T) do {                                                         \
    const float4* p_ = (const float4*)(Wm + bbase + (T) * 16 * 1024);          \
    float4 v0_ = p_[0], v1_ = p_[1];                                           \
    fb[0]=v0_.x; fb[1]=v0_.y; fb[2]=v0_.z; fb[3]=v0_.w;                        \
    fb[4]=v1_.x; fb[5]=v1_.y; fb[6]=v1_.z; fb[7]=v1_.w;                        \
} while (0)

#define SCVT(STG) do {                                                         \
    __nv_bfloat16* s0_ = smem + (STG) * STG_ELE;                               \
    cvt8(fa, s0_ + sA, s0_ + OFF_AL + sA);                                     \
    cvt8(fb, s0_ + OFF_BH + sB, s0_ + OFF_BL + sB);                            \
} while (0)

    // ---- warp tiling: 2(m) x 4(n); warp tile 64x32; m16n8k16 frags ----
    const int wm = (wid >> 2) * 64;
    const int wn = (wid & 3) * 32;

    // ldmatrix source addresses (stage-0 byte offsets)
    const uint32_t smem_u = s2u(smem);
    const int frow = ((lane >> 3) & 1) * 8 + (lane & 7);   // 8x8 matrix row
    const int fcol = (lane >> 4) * 8;                      // elems
    uint32_t aHi[4], aLo[4], bHi[2], bLo[2];
#pragma unroll
    for (int mt = 0; mt < 4; mt++) {
        const uint32_t off = (uint32_t)(((wm + mt*16 + frow) * KPAD2 + fcol) * 2);
        aHi[mt] = smem_u + off;
        aLo[mt] = smem_u + OFF_AL * 2 + off;
    }
#pragma unroll
    for (int g = 0; g < 2; g++) {
        const uint32_t off = (uint32_t)((frow * NPAD + wn + g*16 + fcol) * 2);
        bHi[g] = smem_u + OFF_BH * 2 + off;
        bLo[g] = smem_u + OFF_BL * 2 + off;
    }

    float acc[4][4][4];
#pragma unroll
    for (int mt = 0; mt < 4; mt++)
#pragma unroll
        for (int ng = 0; ng < 4; ng++)
#pragma unroll
            for (int q = 0; q < 4; q++) acc[mt][ng][q] = 0.0f;

    GLOADA(0);
    GLOADB(0);
    SCVT(0);
    __syncthreads();

    for (int t = 0; t < 64; t++) {
        if (t < 63) { GLOADA(t + 1); GLOADB(t + 1); }   // prefetch (hidden by MMAs)

        {   // compute on stage t&1
            const uint32_t sb = (uint32_t)(t & 1) * STG_BYTES;
            uint32_t ah[4][4], al[4][4], bh[2][4], bl[2][4];
#pragma unroll
            for (int mt = 0; mt < 4; mt++) LDSM4(ah[mt], aHi[mt] + sb);
            LDSM4T(bh[0], bHi[0] + sb);
            LDSM4T(bh[1], bHi[1] + sb);
            // P1: Ah * Bh
#pragma unroll
            for (int mt = 0; mt < 4; mt++)
#pragma unroll
                for (int ng = 0; ng < 4; ng++)
                    MMA16816(acc[mt][ng], ah[mt], bh[ng>>1][(ng&1)*2], bh[ng>>1][(ng&1)*2+1]);
            // P3: Al * Bh
#pragma unroll
            for (int mt = 0; mt < 4; mt++) LDSM4(al[mt], aLo[mt] + sb);
#pragma unroll
            for (int mt = 0; mt < 4; mt++)
#pragma unroll
                for (int ng = 0; ng < 4; ng++)
                    MMA16816(acc[mt][ng], al[mt], bh[ng>>1][(ng&1)*2], bh[ng>>1][(ng&1)*2+1]);
            // P2: Ah * Bl
            LDSM4T(bl[0], bLo[0] + sb);
            LDSM4T(bl[1], bLo[1] + sb);
#pragma unroll
            for (int mt = 0; mt < 4; mt++)
#pragma unroll
                for (int ng = 0; ng < 4; ng++)
                    MMA16816(acc[mt][ng], ah[mt], bl[ng>>1][(ng&1)*2], bl[ng>>1][(ng&1)*2+1]);
        }

        if (t < 63) SCVT((t + 1) & 1);   // fill other stage
        __syncthreads();
    }

    // ---- epilogue: per-warp smem staging (reuse operand smem), scatter ----
    float* ep = (float*)smem + wid * (16 * EPAD);

    const int n0  = bn + wn;                 // multiple of 32
    const int cc  = (lane & 7) * 4;          // 0..28
    const int offn = (n0 >> 6) * st + (n0 & 63) + cc;
    const int offc = n0 + cc;
    const float4 bv = *(const float4*)(bias + n0 + cc);

    const int er = lane >> 2;
    const int ec = 2 * (lane & 3);

#pragma unroll
    for (int mt = 0; mt < 4; mt++) {
#pragma unroll
        for (int ng = 0; ng < 4; ng++) {
            float2 v0, v1;
            v0.x = acc[mt][ng][0]; v0.y = acc[mt][ng][1];
            v1.x = acc[mt][ng][2]; v1.y = acc[mt][ng][3];
            *(float2*)(ep + er * EPAD + ng*8 + ec) = v0;
            *(float2*)(ep + (er + 8) * EPAD + ng*8 + ec) = v1;
        }
        __syncwarp();
#pragma unroll
        for (int i = 0; i < 4; i++) {
            const int rr = i * 4 + (lane >> 3);           // 0..15
            const int m = bm + wm + mt * 16 + rr;
            const float* s = ep + rr * EPAD + cc;
            float4 o;
            o.x = s[0] + bv.x; o.y = s[1] + bv.y;
            o.z = s[2] + bv.z; o.w = s[3] + bv.w;
            const int adr = (sel < 4) ? (row_base(m, s1, s2, s3) + offn)
                                      : (m * 1024 + offc);
            *(float4*)(Y + adr) = o;
        }
        __syncwarp();
    }
#undef GLOADA
#undef GLOADB
#undef SCVT
}

// ---------------------------------------------------------------------------
// mean over positions (deterministic 2-stage)
// ---------------------------------------------------------------------------
__global__ void reduce1()
{
    const int b = blockIdx.x, pc = blockIdx.y, ch = threadIdx.x;
    const int base = b * 4194304 + pc * 131072 + ch;
    float s = 0.0f;
#pragma unroll 4
    for (int p = 0; p < 128; p++) {
        const int idx = base + p * 1024;
        s += g_h[idx] + g_w[idx] + g_d[idx] + g_c[idx];
    }
    g_partial[(b * 32 + pc) * 1024 + ch] = s;
}
__global__ void reduce2()
{
    const int b = blockIdx.x, ch = threadIdx.x;
    float s = 0.0f;
#pragma unroll
    for (int pc = 0; pc < 32; pc++) s += g_partial[(b * 32 + pc) * 1024 + ch];
    g_sum[b * 1024 + ch] = s;
}

// ---------------------------------------------------------------------------
// Gating MLP + softmax (tiny)
// ---------------------------------------------------------------------------
__global__ __launch_bounds__(256)
void mlp_kernel(const float* __restrict__ w1, const float* __restrict__ b1,
                const float* __restrict__ w2, const float* __restrict__ b2)
{
    __shared__ float sv[1024];
    __shared__ float tt[256];
    __shared__ float zs[4096];
    const int b = blockIdx.x, tid = threadIdx.x;

    for (int c = tid; c < 1024; c += 256)
        sv[c] = g_sum[b * 1024 + c] * (1.0f / 4096.0f);
    __syncthreads();
    {
        float acc = b1[tid];
        for (int k = 0; k < 1024; k++) acc += sv[k] * w1[k * 256 + tid];
        tt[tid] = 0.5f * acc * (1.0f + erff(acc * 0.7071067811865476f));
    }
    __syncthreads();
    for (int n = tid; n < 4096; n += 256) {
        float acc = b2[n];
#pragma unroll 8
        for (int k = 0; k < 256; k++) acc += tt[k] * w2[k * 4096 + n];
        zs[n] = acc;
    }
    __syncthreads();
    for (int c = tid; c < 1024; c += 256) {
        const float v0 = zs[4*c+0], v1 = zs[4*c+1], v2 = zs[4*c+2], v3 = zs[4*c+3];
        const float mx = fmaxf(fmaxf(v0, v1), fmaxf(v2, v3));
        const float e0 = expf(v0-mx), e1 = expf(v1-mx), e2 = expf(v2-mx), e3 = expf(v3-mx);
        const float inv = 1.0f / (e0 + e1 + e2 + e3);
        g_a[0*8192 + b*1024 + c] = e0 * inv;
        g_a[1*8192 + b*1024 + c] = e1 * inv;
        g_a[2*8192 + b*1024 + c] = e2 * inv;
        g_a[3*8192 + b*1024 + c] = e3 * inv;
    }
}

// ---------------------------------------------------------------------------
extern "C" void kernel_launch(void* const* d_in, const int* in_sizes, int n_in,
                              void* d_out, int out_size)
{
    const float* x  = (const float*)d_in[0];
    const float* wh = (const float*)d_in[1];
    const float* bh = (const float*)d_in[2];
    const float* ww = (const float*)d_in[3];
    const float* bw = (const float*)d_in[4];
    const float* wd = (const float*)d_in[5];
    const float* bd = (const float*)d_in[6];
    const float* wc = (const float*)d_in[7];
    const float* bc = (const float*)d_in[8];
    const float* w1 = (const float*)d_in[9];
    const float* b1 = (const float*)d_in[10];
    const float* w2 = (const float*)d_in[11];
    const float* b2 = (const float*)d_in[12];
    const float* wp = (const float*)d_in[13];
    const float* bp = (const float*)d_in[14];
    float* out = (float*)d_out;

    dim3 grid(8, 256);

    // branch GEMMs: h, w, d, c
    gemm_mma<<<grid, 256>>>(x, wh, bh, 0, 64,     16384, 1024, 262144, nullptr);
    gemm_mma<<<grid, 256>>>(x, ww, bw, 1, 262144, 64,    1024, 16384,  nullptr);
    gemm_mma<<<grid, 256>>>(x, wd, bd, 2, 262144, 16384, 64,   1024,   nullptr);
    gemm_mma<<<grid, 256>>>(x, wc, bc, 3, 262144, 16384, 1024, 64,     nullptr);

    // mean + gating
    reduce1<<<dim3(8, 32), 1024>>>();
    reduce2<<<8, 1024>>>();
    mlp_kernel<<<8, 256>>>(w1, b1, w2, b2);

    // final projection with fused weighted combine
    gemm_mma<<<grid, 256>>>(x, wp, bp, 4, 262144, 16384, 1024, 64, out);
}

// round 12
// speedup vs baseline: 1.8475x; 1.0900x over previous
#include <cuda_runtime.h>
#include <cuda_bf16.h>
#include <cstdint>
#include <math.h>

// ===========================================================================
// WeightedPermuteMLP — split-bf16, ldmatrix + mma.sync.m16n8k16.
// R12: vectorized STS.128 tile stores; parallelized reduce/MLP glue kernels.
// D = Ah*Bh + Ah*Bl + Al*Bh (fp32 accum), rel_err ~1e-5.
// ===========================================================================

#define NELEM 33554432

__device__ __align__(256) float g_h[NELEM];
__device__ __align__(256) float g_w[NELEM];
__device__ __align__(256) float g_d[NELEM];
__device__ __align__(256) float g_c[NELEM];
__device__ __align__(256) float g_partial[8 * 128 * 1024];
__device__ __align__(256) float g_sum[8 * 1024];
__device__ __align__(256) float g_t[8 * 256];
__device__ __align__(256) float g_a[4 * 8 * 1024];   // [q][b][chan]

__device__ __forceinline__ int row_base(int m, int s1, int s2, int s3) {
    return (m >> 12) * 4194304 + ((m >> 8) & 15) * s1 + ((m >> 4) & 15) * s2 + (m & 15) * s3;
}

__device__ __forceinline__ uint32_t s2u(const void* p) {
    uint32_t a;
    asm("{ .reg .u64 t; cvta.to.shared.u64 t, %1; cvt.u32.u64 %0, t; }" : "=r"(a) : "l"(p));
    return a;
}

// split 8 fp32 -> bf16 hi/lo, packed into one uint4 each (16B)
__device__ __forceinline__ void cvt8v(const float* f, uint4& hv, uint4& lv)
{
    uint32_t h[4], l[4];
#pragma unroll
    for (int j = 0; j < 4; j++) {
        const float x0 = f[2*j], x1 = f[2*j+1];
        const __nv_bfloat16 h0 = __float2bfloat16_rn(x0);
        const __nv_bfloat16 h1 = __float2bfloat16_rn(x1);
        __nv_bfloat162 hh = __halves2bfloat162(h0, h1);
        __nv_bfloat162 ll = __halves2bfloat162(
            __float2bfloat16_rn(x0 - __bfloat162float(h0)),
            __float2bfloat16_rn(x1 - __bfloat162float(h1)));
        h[j] = *reinterpret_cast<uint32_t*>(&hh);
        l[j] = *reinterpret_cast<uint32_t*>(&ll);
    }
    hv = make_uint4(h[0], h[1], h[2], h[3]);
    lv = make_uint4(l[0], l[1], l[2], l[3]);
}

#define LDSM4(R, ADDR) \
    asm volatile("ldmatrix.sync.aligned.m8n8.x4.shared.b16 {%0,%1,%2,%3}, [%4];" \
                 : "=r"((R)[0]), "=r"((R)[1]), "=r"((R)[2]), "=r"((R)[3]) : "r"(ADDR))
#define LDSM4T(R, ADDR) \
    asm volatile("ldmatrix.sync.aligned.m8n8.x4.trans.shared.b16 {%0,%1,%2,%3}, [%4];" \
                 : "=r"((R)[0]), "=r"((R)[1]), "=r"((R)[2]), "=r"((R)[3]) : "r"(ADDR))
#define MMA16816(D, A, B0, B1) \
    asm volatile("mma.sync.aligned.m16n8k16.row.col.f32.bf16.bf16.f32 " \
                 "{%0,%1,%2,%3}, {%4,%5,%6,%7}, {%8,%9}, {%0,%1,%2,%3};" \
                 : "+f"((D)[0]), "+f"((D)[1]), "+f"((D)[2]), "+f"((D)[3]) \
                 : "r"((A)[0]), "r"((A)[1]), "r"((A)[2]), "r"((A)[3]), "r"(B0), "r"(B1))

// ---------------------------------------------------------------------------
// Unified GEMM: block 128x128, BK=16, 8 warps (2m x 4n), warp tile 64x32.
// Double-buffered static smem: 2 stages x 20992 B = 41984 B; 2 CTAs/SM.
// ---------------------------------------------------------------------------
#define KPAD2 24
#define NPAD 136
#define A_ELE (128 * KPAD2)
#define B_ELE (16 * NPAD)
#define STG_ELE (2 * A_ELE + 2 * B_ELE)
#define STG_BYTES (STG_ELE * 2)
#define OFF_AL A_ELE
#define OFF_BH (2 * A_ELE)
#define OFF_BL (2 * A_ELE + B_ELE)
#define EPAD 36

__global__ __launch_bounds__(256, 2)
void gemm_mma(const float* __restrict__ X, const float* __restrict__ Wm,
              const float* __restrict__ bias, int sel,
              int s1, int s2, int s3, int st, float* __restrict__ outF)
{
    __shared__ __align__(256) __nv_bfloat16 smem[2 * STG_ELE];

    const int tid = threadIdx.x;
    const int wid = tid >> 5;
    const int lane = tid & 31;
    const int bm = blockIdx.y * 128;
    const int bn = blockIdx.x * 128;
    float* Y = (sel == 0) ? g_h : (sel == 1) ? g_w : (sel == 2) ? g_d
             : (sel == 3) ? g_c : outF;

    const int r  = tid >> 1;
    const int lk = (tid & 1) * 8;
    const int abase = row_base(bm + r, s1, s2, s3) + lk;
    const int cbase = (bm + r) * 1024 + lk;
    const int awbase = ((bm >> 12) << 10) + lk;
    const int sA = r * KPAD2 + lk;

    const int krow = tid >> 4;
    const int ncol = (tid & 15) * 8;
    const int bbase = krow * 1024 + bn + ncol;
    const int sB = krow * NPAD + ncol;

    float fa[8], fb[8];

#define GLOADA(T) do {                                                         \
    if (sel < 4) {                                                             \
        const float4* p_ = (const float4*)(X + abase + ((T) >> 2) * st + ((T) & 3) * 16); \
        float4 v0_ = p_[0], v1_ = p_[1];                                       \
        fa[0]=v0_.x; fa[1]=v0_.y; fa[2]=v0_.z; fa[3]=v0_.w;                    \
        fa[4]=v1_.x; fa[5]=v1_.y; fa[6]=v1_.z; fa[7]=v1_.w;                    \
    } else {                                                                   \
        const int i0_ = cbase + (T) * 16;                                      \
        const int aw_ = awbase + (T) * 16;                                     \
        _Pragma("unroll")                                                      \
        for (int q_ = 0; q_ < 2; q_++) {                                       \
            float4 h_ = *(const float4*)(g_h + i0_ + 4*q_);                    \
            float4 w_ = *(const float4*)(g_w + i0_ + 4*q_);                    \
            float4 d_ = *(const float4*)(g_d + i0_ + 4*q_);                    \
            float4 c_ = *(const float4*)(g_c + i0_ + 4*q_);                    \
            float4 a0_ = *(const float4*)(g_a + 0*8192 + aw_ + 4*q_);          \
            float4 a1_ = *(const float4*)(g_a + 1*8192 + aw_ + 4*q_);          \
            float4 a2_ = *(const float4*)(g_a + 2*8192 + aw_ + 4*q_);          \
            float4 a3_ = *(const float4*)(g_a + 3*8192 + aw_ + 4*q_);          \
            fa[4*q_+0] = h_.x*a0_.x + w_.x*a1_.x + d_.x*a2_.x + c_.x*a3_.x;    \
            fa[4*q_+1] = h_.y*a0_.y + w_.y*a1_.y + d_.y*a2_.y + c_.y*a3_.y;    \
            fa[4*q_+2] = h_.z*a0_.z + w_.z*a1_.z + d_.z*a2_.z + c_.z*a3_.z;    \
            fa[4*q_+3] = h_.w*a0_.w + w_.w*a1_.w + d_.w*a2_.w + c_.w*a3_.w;    \
        }                                                                      \
    }                                                                          \
} while (0)

#define GLOADB(T) do {                                                         \
    const float4* p_ = (const float4*)(Wm + bbase + (T) * 16 * 1024);          \
    float4 v0_ = p_[0], v1_ = p_[1];                                           \
    fb[0]=v0_.x; fb[1]=v0_.y; fb[2]=v0_.z; fb[3]=v0_.w;                        \
    fb[4]=v1_.x; fb[5]=v1_.y; fb[6]=v1_.z; fb[7]=v1_.w;                        \
} while (0)

#define SCVT(STG) do {                                                         \
    __nv_bfloat16* s0_ = smem + (STG) * STG_ELE;                               \
    uint4 hA_, lA_, hB_, lB_;                                                  \
    cvt8v(fa, hA_, lA_);                                                       \
    cvt8v(fb, hB_, lB_);                                                       \
    *(uint4*)(s0_ + sA) = hA_;                                                 \
    *(uint4*)(s0_ + OFF_AL + sA) = lA_;                                        \
    *(uint4*)(s0_ + OFF_BH + sB) = hB_;                                        \
    *(uint4*)(s0_ + OFF_BL + sB) = lB_;                                        \
} while (0)

    const int wm = (wid >> 2) * 64;
    const int wn = (wid & 3) * 32;

    const uint32_t smem_u = s2u(smem);
    const int frow = ((lane >> 3) & 1) * 8 + (lane & 7);
    const int fcol = (lane >> 4) * 8;
    uint32_t aHi[4], aLo[4], bHi[2], bLo[2];
#pragma unroll
    for (int mt = 0; mt < 4; mt++) {
        const uint32_t off = (uint32_t)(((wm + mt*16 + frow) * KPAD2 + fcol) * 2);
        aHi[mt] = smem_u + off;
        aLo[mt] = smem_u + OFF_AL * 2 + off;
    }
#pragma unroll
    for (int g = 0; g < 2; g++) {
        const uint32_t off = (uint32_t)((frow * NPAD + wn + g*16 + fcol) * 2);
        bHi[g] = smem_u + OFF_BH * 2 + off;
        bLo[g] = smem_u + OFF_BL * 2 + off;
    }

    float acc[4][4][4];
#pragma unroll
    for (int mt = 0; mt < 4; mt++)
#pragma unroll
        for (int ng = 0; ng < 4; ng++)
#pragma unroll
            for (int q = 0; q < 4; q++) acc[mt][ng][q] = 0.0f;

    GLOADA(0);
    GLOADB(0);
    SCVT(0);
    __syncthreads();

    for (int t = 0; t < 64; t++) {
        if (t < 63) { GLOADA(t + 1); GLOADB(t + 1); }

        {
            const uint32_t sb = (uint32_t)(t & 1) * STG_BYTES;
            uint32_t ah[4][4], al[4][4], bh[2][4], bl[2][4];
#pragma unroll
            for (int mt = 0; mt < 4; mt++) LDSM4(ah[mt], aHi[mt] + sb);
            LDSM4T(bh[0], bHi[0] + sb);
            LDSM4T(bh[1], bHi[1] + sb);
#pragma unroll
            for (int mt = 0; mt < 4; mt++)
#pragma unroll
                for (int ng = 0; ng < 4; ng++)
                    MMA16816(acc[mt][ng], ah[mt], bh[ng>>1][(ng&1)*2], bh[ng>>1][(ng&1)*2+1]);
#pragma unroll
            for (int mt = 0; mt < 4; mt++) LDSM4(al[mt], aLo[mt] + sb);
#pragma unroll
            for (int mt = 0; mt < 4; mt++)
#pragma unroll
                for (int ng = 0; ng < 4; ng++)
                    MMA16816(acc[mt][ng], al[mt], bh[ng>>1][(ng&1)*2], bh[ng>>1][(ng&1)*2+1]);
            LDSM4T(bl[0], bLo[0] + sb);
            LDSM4T(bl[1], bLo[1] + sb);
#pragma unroll
            for (int mt = 0; mt < 4; mt++)
#pragma unroll
                for (int ng = 0; ng < 4; ng++)
                    MMA16816(acc[mt][ng], ah[mt], bl[ng>>1][(ng&1)*2], bl[ng>>1][(ng&1)*2+1]);
        }

        if (t < 63) SCVT((t + 1) & 1);
        __syncthreads();
    }

    // ---- epilogue ----
    float* ep = (float*)smem + wid * (16 * EPAD);

    const int n0  = bn + wn;
    const int cc  = (lane & 7) * 4;
    const int offn = (n0 >> 6) * st + (n0 & 63) + cc;
    const int offc = n0 + cc;
    const float4 bv = *(const float4*)(bias + n0 + cc);

    const int er = lane >> 2;
    const int ec = 2 * (lane & 3);

#pragma unroll
    for (int mt = 0; mt < 4; mt++) {
#pragma unroll
        for (int ng = 0; ng < 4; ng++) {
            float2 v0, v1;
            v0.x = acc[mt][ng][0]; v0.y = acc[mt][ng][1];
            v1.x = acc[mt][ng][2]; v1.y = acc[mt][ng][3];
            *(float2*)(ep + er * EPAD + ng*8 + ec) = v0;
            *(float2*)(ep + (er + 8) * EPAD + ng*8 + ec) = v1;
        }
        __syncwarp();
#pragma unroll
        for (int i = 0; i < 4; i++) {
            const int rr = i * 4 + (lane >> 3);
            const int m = bm + wm + mt * 16 + rr;
            const float* s = ep + rr * EPAD + cc;
            float4 o;
            o.x = s[0] + bv.x; o.y = s[1] + bv.y;
            o.z = s[2] + bv.z; o.w = s[3] + bv.w;
            const int adr = (sel < 4) ? (row_base(m, s1, s2, s3) + offn)
                                      : (m * 1024 + offc);
            *(float4*)(Y + adr) = o;
        }
        __syncwarp();
    }
#undef GLOADA
#undef GLOADB
#undef SCVT
}

// ---------------------------------------------------------------------------
// mean over positions — stage 1: grid (8,128), block 1024; 32 p each
// ---------------------------------------------------------------------------
__global__ __launch_bounds__(1024)
void reduce1()
{
    const int b = blockIdx.x, pc = blockIdx.y, ch = threadIdx.x;
    const int base = b * 4194304 + pc * 32768 + ch;
    float s = 0.0f;
#pragma unroll 8
    for (int p = 0; p < 32; p++) {
        const int idx = base + p * 1024;
        s += g_h[idx] + g_w[idx] + g_d[idx] + g_c[idx];
    }
    g_partial[(b * 128 + pc) * 1024 + ch] = s;
}

// stage 2: grid (8,4), block 256
__global__ __launch_bounds__(256)
void reduce2()
{
    const int b = blockIdx.x, ch = blockIdx.y * 256 + threadIdx.x;
    float s = 0.0f;
#pragma unroll 16
    for (int pc = 0; pc < 128; pc++) s += g_partial[(b * 128 + pc) * 1024 + ch];
    g_sum[b * 1024 + ch] = s;
}

// ---------------------------------------------------------------------------
// Gating MLP stage 1: t = gelu(mean @ w1 + b1).  grid 8, block 1024.
// 4 threads per output (k-split), smem reduce.
// ---------------------------------------------------------------------------
__global__ __launch_bounds__(1024)
void mlp1(const float* __restrict__ w1, const float* __restrict__ b1)
{
    __shared__ float sv[1024];
    __shared__ float red[4][256];
    const int b = blockIdx.x, tid = threadIdx.x;

    sv[tid] = g_sum[b * 1024 + tid] * (1.0f / 4096.0f);
    __syncthreads();

    const int o = tid & 255, part = tid >> 8;
    float acc = 0.0f;
    const float* wp = w1 + (part * 256) * 256 + o;
    const float* svp = sv + part * 256;
#pragma unroll 8
    for (int kk = 0; kk < 256; kk++) acc += svp[kk] * wp[kk * 256];
    red[part][o] = acc;
    __syncthreads();

    if (tid < 256) {
        float a = red[0][tid] + red[1][tid] + red[2][tid] + red[3][tid] + b1[tid];
        g_t[b * 256 + tid] = 0.5f * a * (1.0f + erff(a * 0.7071067811865476f));
    }
}

// ---------------------------------------------------------------------------
// Gating MLP stage 2 + softmax: grid (8,16), block 256.
// z = t @ w2 + b2 (this block's 256 n's), softmax over q groups of 4.
// ---------------------------------------------------------------------------
__global__ __launch_bounds__(256)
void mlp2(const float* __restrict__ w2, const float* __restrict__ b2)
{
    __shared__ float tt[256];
    __shared__ float zs[256];
    const int b = blockIdx.x, ny = blockIdx.y, tid = threadIdx.x;

    tt[tid] = g_t[b * 256 + tid];
    __syncthreads();

    const int n = ny * 256 + tid;
    float acc = b2[n];
#pragma unroll 8
    for (int k = 0; k < 256; k++) acc += tt[k] * w2[k * 4096 + n];
    zs[tid] = acc;
    __syncthreads();

    if (tid < 64) {
        const int c = ny * 64 + tid;
        const float v0 = zs[4*tid+0], v1 = zs[4*tid+1], v2 = zs[4*tid+2], v3 = zs[4*tid+3];
        const float mx = fmaxf(fmaxf(v0, v1), fmaxf(v2, v3));
        const float e0 = expf(v0-mx), e1 = expf(v1-mx), e2 = expf(v2-mx), e3 = expf(v3-mx);
        const float inv = 1.0f / (e0 + e1 + e2 + e3);
        g_a[0*8192 + b*1024 + c] = e0 * inv;
        g_a[1*8192 + b*1024 + c] = e1 * inv;
        g_a[2*8192 + b*1024 + c] = e2 * inv;
        g_a[3*8192 + b*1024 + c] = e3 * inv;
    }
}

// ---------------------------------------------------------------------------
extern "C" void kernel_launch(void* const* d_in, const int* in_sizes, int n_in,
                              void* d_out, int out_size)
{
    const float* x  = (const float*)d_in[0];
    const float* wh = (const float*)d_in[1];
    const float* bh = (const float*)d_in[2];
    const float* ww = (const float*)d_in[3];
    const float* bw = (const float*)d_in[4];
    const float* wd = (const float*)d_in[5];
    const float* bd = (const float*)d_in[6];
    const float* wc = (const float*)d_in[7];
    const float* bc = (const float*)d_in[8];
    const float* w1 = (const float*)d_in[9];
    const float* b1 = (const float*)d_in[10];
    const float* w2 = (const float*)d_in[11];
    const float* b2 = (const float*)d_in[12];
    const float* wp = (const float*)d_in[13];
    const float* bp = (const float*)d_in[14];
    float* out = (float*)d_out;

    dim3 grid(8, 256);

    // branch GEMMs: h, w, d, c
    gemm_mma<<<grid, 256>>>(x, wh, bh, 0, 64,     16384, 1024, 262144, nullptr);
    gemm_mma<<<grid, 256>>>(x, ww, bw, 1, 262144, 64,    1024, 16384,  nullptr);
    gemm_mma<<<grid, 256>>>(x, wd, bd, 2, 262144, 16384, 64,   1024,   nullptr);
    gemm_mma<<<grid, 256>>>(x, wc, bc, 3, 262144, 16384, 1024, 64,     nullptr);

    // mean + gating (parallelized)
    reduce1<<<dim3(8, 128), 1024>>>();
    reduce2<<<dim3(8, 4), 256>>>();
    mlp1<<<8, 1024>>>(w1, b1);
    mlp2<<<dim3(8, 16), 256>>>(w2, b2);

    // final projection with fused weighted combine
    gemm_mma<<<grid, 256>>>(x, wp, bp, 4, 262144, 16384, 1024, 64, out);
}

// round 13
// speedup vs baseline: 2.0502x; 1.1097x over previous
#include <cuda_runtime.h>
#include <cuda_bf16.h>
#include <cstdint>
#include <math.h>

// ===========================================================================
// WeightedPermuteMLP — split-bf16 ldmatrix+mma.sync, gating-first schedule.
// Mean commutes with the branch GEMMs:
//   mean_m(A_q @ Wq) = (partial sums of x) @ (position-summed Wq)
// so the softmax gate a_q is computed BEFORE the big GEMMs from tiny
// reductions. Branch GEMM epilogues then apply a_q and accumulate directly
// into one comb buffer (g_h); final projection is a plain GEMM on comb.
// D = Ah*Bh + Ah*Bl + Al*Bh (fp32 accum), rel_err ~1e-5.
// ===========================================================================

#define NELEM 33554432

__device__ __align__(256) float g_h[NELEM];            // comb accumulator
__device__ __align__(256) float g_smh[8 * 16 * 1024];  // sum over (w,d)
__device__ __align__(256) float g_smw4[4 * 8 * 16 * 1024]; // partial over hh-groups
__device__ __align__(256) float g_smd4[4 * 8 * 16 * 1024];
__device__ __align__(256) float g_sp4[4 * 8 * 1024];
__device__ __align__(256) float g_sw[3 * 65536];       // [z][k'*64+s] summed weights
__device__ __align__(256) float g_sum[8 * 1024];
__device__ __align__(256) float g_t[8 * 256];
__device__ __align__(256) float g_a[4 * 8 * 1024];     // [q][b][chan]

__device__ __forceinline__ int row_base(int m, int s1, int s2, int s3) {
    return (m >> 12) * 4194304 + ((m >> 8) & 15) * s1 + ((m >> 4) & 15) * s2 + (m & 15) * s3;
}

__device__ __forceinline__ uint32_t s2u(const void* p) {
    uint32_t a;
    asm("{ .reg .u64 t; cvta.to.shared.u64 t, %1; cvt.u32.u64 %0, t; }" : "=r"(a) : "l"(p));
    return a;
}

__device__ __forceinline__ void cvt8v(const float* f, uint4& hv, uint4& lv)
{
    uint32_t h[4], l[4];
#pragma unroll
    for (int j = 0; j < 4; j++) {
        const float x0 = f[2*j], x1 = f[2*j+1];
        const __nv_bfloat16 h0 = __float2bfloat16_rn(x0);
        const __nv_bfloat16 h1 = __float2bfloat16_rn(x1);
        __nv_bfloat162 hh = __halves2bfloat162(h0, h1);
        __nv_bfloat162 ll = __halves2bfloat162(
            __float2bfloat16_rn(x0 - __bfloat162float(h0)),
            __float2bfloat16_rn(x1 - __bfloat162float(h1)));
        h[j] = *reinterpret_cast<uint32_t*>(&hh);
        l[j] = *reinterpret_cast<uint32_t*>(&ll);
    }
    hv = make_uint4(h[0], h[1], h[2], h[3]);
    lv = make_uint4(l[0], l[1], l[2], l[3]);
}

#define LDSM4(R, ADDR) \
    asm volatile("ldmatrix.sync.aligned.m8n8.x4.shared.b16 {%0,%1,%2,%3}, [%4];" \
                 : "=r"((R)[0]), "=r"((R)[1]), "=r"((R)[2]), "=r"((R)[3]) : "r"(ADDR))
#define LDSM4T(R, ADDR) \
    asm volatile("ldmatrix.sync.aligned.m8n8.x4.trans.shared.b16 {%0,%1,%2,%3}, [%4];" \
                 : "=r"((R)[0]), "=r"((R)[1]), "=r"((R)[2]), "=r"((R)[3]) : "r"(ADDR))
#define MMA16816(D, A, B0, B1) \
    asm volatile("mma.sync.aligned.m16n8k16.row.col.f32.bf16.bf16.f32 " \
                 "{%0,%1,%2,%3}, {%4,%5,%6,%7}, {%8,%9}, {%0,%1,%2,%3};" \
                 : "+f"((D)[0]), "+f"((D)[1]), "+f"((D)[2]), "+f"((D)[3]) \
                 : "r"((A)[0]), "r"((A)[1]), "r"((A)[2]), "r"((A)[3]), "r"(B0), "r"(B1))

// ---------------------------------------------------------------------------
// GEMM: block 128x128, BK=16, 8 warps (2m x 4n), warp tile 64x32.
//  sel 0..3 (h,w,d,c): A = gather from X; epilogue: o = a_sel*(Z+bias),
//    accumulated into g_h (sel>0 reads previous value; launched in order).
//  sel 4: plain GEMM, A = g_h (comb) contiguous, write outF.
// ---------------------------------------------------------------------------
#define KPAD2 24
#define NPAD 136
#define A_ELE (128 * KPAD2)
#define B_ELE (16 * NPAD)
#define STG_ELE (2 * A_ELE + 2 * B_ELE)
#define STG_BYTES (STG_ELE * 2)
#define OFF_AL A_ELE
#define OFF_BH (2 * A_ELE)
#define OFF_BL (2 * A_ELE + B_ELE)
#define EPAD 36

__global__ __launch_bounds__(256, 2)
void gemm_mma(const float* __restrict__ X, const float* __restrict__ Wm,
              const float* __restrict__ bias, int sel,
              int s1, int s2, int s3, int st, float* __restrict__ outF)
{
    __shared__ __align__(256) __nv_bfloat16 smem[2 * STG_ELE];

    const int tid = threadIdx.x;
    const int wid = tid >> 5;
    const int lane = tid & 31;
    const int bm = blockIdx.y * 128;
    const int bn = blockIdx.x * 128;

    const int r  = tid >> 1;
    const int lk = (tid & 1) * 8;
    const int abase = row_base(bm + r, s1, s2, s3) + lk;
    const int cbase = (bm + r) * 1024 + lk;
    const int sA = r * KPAD2 + lk;

    const int krow = tid >> 4;
    const int ncol = (tid & 15) * 8;
    const int bbase = krow * 1024 + bn + ncol;
    const int sB = krow * NPAD + ncol;

    float fa[8], fb[8];

#define GLOADA(T) do {                                                         \
    if (sel < 4) {                                                             \
        const float4* p_ = (const float4*)(X + abase + ((T) >> 2) * st + ((T) & 3) * 16); \
        float4 v0_ = p_[0], v1_ = p_[1];                                       \
        fa[0]=v0_.x; fa[1]=v0_.y; fa[2]=v0_.z; fa[3]=v0_.w;                    \
        fa[4]=v1_.x; fa[5]=v1_.y; fa[6]=v1_.z; fa[7]=v1_.w;                    \
    } else {                                                                   \
        const float4* p_ = (const float4*)(g_h + cbase + (T) * 16);            \
        float4 v0_ = p_[0], v1_ = p_[1];                                       \
        fa[0]=v0_.x; fa[1]=v0_.y; fa[2]=v0_.z; fa[3]=v0_.w;                    \
        fa[4]=v1_.x; fa[5]=v1_.y; fa[6]=v1_.z; fa[7]=v1_.w;                    \
    }                                                                          \
} while (0)

#define GLOADB(T) do {                                                         \
    const float4* p_ = (const float4*)(Wm + bbase + (T) * 16 * 1024);          \
    float4 v0_ = p_[0], v1_ = p_[1];                                           \
    fb[0]=v0_.x; fb[1]=v0_.y; fb[2]=v0_.z; fb[3]=v0_.w;                        \
    fb[4]=v1_.x; fb[5]=v1_.y; fb[6]=v1_.z; fb[7]=v1_.w;                        \
} while (0)

#define SCVT(STG) do {                                                         \
    __nv_bfloat16* s0_ = smem + (STG) * STG_ELE;                               \
    uint4 hA_, lA_, hB_, lB_;                                                  \
    cvt8v(fa, hA_, lA_);                                                       \
    cvt8v(fb, hB_, lB_);                                                       \
    *(uint4*)(s0_ + sA) = hA_;                                                 \
    *(uint4*)(s0_ + OFF_AL + sA) = lA_;                                        \
    *(uint4*)(s0_ + OFF_BH + sB) = hB_;                                        \
    *(uint4*)(s0_ + OFF_BL + sB) = lB_;                                        \
} while (0)

    const int wm = (wid >> 2) * 64;
    const int wn = (wid & 3) * 32;

    const uint32_t smem_u = s2u(smem);
    const int frow = ((lane >> 3) & 1) * 8 + (lane & 7);
    const int fcol = (lane >> 4) * 8;
    uint32_t aHi[4], aLo[4], bHi[2], bLo[2];
#pragma unroll
    for (int mt = 0; mt < 4; mt++) {
        const uint32_t off = (uint32_t)(((wm + mt*16 + frow) * KPAD2 + fcol) * 2);
        aHi[mt] = smem_u + off;
        aLo[mt] = smem_u + OFF_AL * 2 + off;
    }
#pragma unroll
    for (int g = 0; g < 2; g++) {
        const uint32_t off = (uint32_t)((frow * NPAD + wn + g*16 + fcol) * 2);
        bHi[g] = smem_u + OFF_BH * 2 + off;
        bLo[g] = smem_u + OFF_BL * 2 + off;
    }

    float acc[4][4][4];
#pragma unroll
    for (int mt = 0; mt < 4; mt++)
#pragma unroll
        for (int ng = 0; ng < 4; ng++)
#pragma unroll
            for (int q = 0; q < 4; q++) acc[mt][ng][q] = 0.0f;

    GLOADA(0);
    GLOADB(0);
    SCVT(0);
    __syncthreads();

    for (int t = 0; t < 64; t++) {
        if (t < 63) { GLOADA(t + 1); GLOADB(t + 1); }

        {
            const uint32_t sb = (uint32_t)(t & 1) * STG_BYTES;
            uint32_t ah[4][4], al[4][4], bh[2][4], bl[2][4];
#pragma unroll
            for (int mt = 0; mt < 4; mt++) LDSM4(ah[mt], aHi[mt] + sb);
            LDSM4T(bh[0], bHi[0] + sb);
            LDSM4T(bh[1], bHi[1] + sb);
#pragma unroll
            for (int mt = 0; mt < 4; mt++)
#pragma unroll
                for (int ng = 0; ng < 4; ng++)
                    MMA16816(acc[mt][ng], ah[mt], bh[ng>>1][(ng&1)*2], bh[ng>>1][(ng&1)*2+1]);
#pragma unroll
            for (int mt = 0; mt < 4; mt++) LDSM4(al[mt], aLo[mt] + sb);
#pragma unroll
            for (int mt = 0; mt < 4; mt++)
#pragma unroll
                for (int ng = 0; ng < 4; ng++)
                    MMA16816(acc[mt][ng], al[mt], bh[ng>>1][(ng&1)*2], bh[ng>>1][(ng&1)*2+1]);
            LDSM4T(bl[0], bLo[0] + sb);
            LDSM4T(bl[1], bLo[1] + sb);
#pragma unroll
            for (int mt = 0; mt < 4; mt++)
#pragma unroll
                for (int ng = 0; ng < 4; ng++)
                    MMA16816(acc[mt][ng], ah[mt], bl[ng>>1][(ng&1)*2], bl[ng>>1][(ng&1)*2+1]);
        }

        if (t < 63) SCVT((t + 1) & 1);
        __syncthreads();
    }

    // ---- epilogue ----
    float* ep = (float*)smem + wid * (16 * EPAD);

    const int n0  = bn + wn;
    const int cc  = (lane & 7) * 4;
    const int offn = (n0 >> 6) * st + (n0 & 63) + cc;
    const int offc = n0 + cc;
    const float4 bv = *(const float4*)(bias + n0 + cc);

    const int er = lane >> 2;
    const int ec = 2 * (lane & 3);

    const int bq = bm >> 12;
    const int scol = (n0 & 63) + cc;
    const int by = blockIdx.y;
    const int sig0 = (by >> 1) & 15;              // sel0 (h): channel-sigma const/CTA
    const int sig1b = by * 8 + 4 * (wid >> 2);    // sel1 (w): + mt

#pragma unroll
    for (int mt = 0; mt < 4; mt++) {
#pragma unroll
        for (int ng = 0; ng < 4; ng++) {
            float2 v0, v1;
            v0.x = acc[mt][ng][0]; v0.y = acc[mt][ng][1];
            v1.x = acc[mt][ng][2]; v1.y = acc[mt][ng][3];
            *(float2*)(ep + er * EPAD + ng*8 + ec) = v0;
            *(float2*)(ep + (er + 8) * EPAD + ng*8 + ec) = v1;
        }
        __syncwarp();
        const int sig_mt = (sig1b + mt) & 15;
#pragma unroll
        for (int i = 0; i < 4; i++) {
            const int rr = i * 4 + (lane >> 3);
            const int m = bm + wm + mt * 16 + rr;
            const float* s = ep + rr * EPAD + cc;
            if (sel < 4) {
                const int ch = (sel == 0) ? (sig0 * 64 + scol)
                             : (sel == 1) ? (sig_mt * 64 + scol)
                             : (sel == 2) ? (rr * 64 + scol)
                             : offc;
                const float4 av = *(const float4*)(g_a + (sel << 13) + (bq << 10) + ch);
                const int adr = row_base(m, s1, s2, s3) + offn;
                float4 o;
                o.x = av.x * (s[0] + bv.x);
                o.y = av.y * (s[1] + bv.y);
                o.z = av.z * (s[2] + bv.z);
                o.w = av.w * (s[3] + bv.w);
                if (sel > 0) {
                    const float4 pv = *(const float4*)(g_h + adr);
                    o.x += pv.x; o.y += pv.y; o.z += pv.z; o.w += pv.w;
                }
                *(float4*)(g_h + adr) = o;
            } else {
                float4 o;
                o.x = s[0] + bv.x; o.y = s[1] + bv.y;
                o.z = s[2] + bv.z; o.w = s[3] + bv.w;
                *(float4*)(outF + m * 1024 + offc) = o;
            }
        }
        __syncwarp();
    }
#undef GLOADA
#undef GLOADB
#undef SCVT
}

// ---------------------------------------------------------------------------
// Partial sums of x: SMh[b,hh,c]=Σ_{w,d}; SMw/SMd partial per hh-group; SP.
// grid (8, 8, 4), 128 threads.
// ---------------------------------------------------------------------------
__global__ __launch_bounds__(128)
void psum_kernel(const float* __restrict__ X)
{
    const int b = blockIdx.x, cg = blockIdx.y, hg = blockIdx.z;
    const int c = cg * 128 + threadIdx.x;
    float sw[16], sd[16];
#pragma unroll
    for (int i = 0; i < 16; i++) { sw[i] = 0.0f; sd[i] = 0.0f; }
    float sp = 0.0f;
    const float* xb = X + (size_t)b * 4194304 + c;
    for (int hl = 0; hl < 4; hl++) {
        const int hh = hg * 4 + hl;
        float sh = 0.0f;
        const float* xh = xb + hh * 262144;
#pragma unroll
        for (int ww = 0; ww < 16; ww++)
#pragma unroll
            for (int dd = 0; dd < 16; dd++) {
                float v = xh[ww * 16384 + dd * 1024];
                sh += v; sw[ww] += v; sd[dd] += v;
            }
        g_smh[(b * 16 + hh) * 1024 + c] = sh;
        sp += sh;
    }
#pragma unroll
    for (int i = 0; i < 16; i++) {
        g_smw4[((hg * 8 + b) * 16 + i) * 1024 + c] = sw[i];
        g_smd4[((hg * 8 + b) * 16 + i) * 1024 + c] = sd[i];
    }
    g_sp4[(hg * 8 + b) * 1024 + c] = sp;
}

// ---------------------------------------------------------------------------
// Position-summed weights: g_sw[z][k'*64+s] = Σ_p Wz[k', p*64+s]
// ---------------------------------------------------------------------------
__global__ __launch_bounds__(64)
void wred_kernel(const float* __restrict__ w0, const float* __restrict__ w1,
                 const float* __restrict__ w2)
{
    const int kp = blockIdx.x, z = blockIdx.y, s = threadIdx.x;
    const float* W = (z == 0) ? w0 : (z == 1) ? w1 : w2;
    float acc = 0.0f;
#pragma unroll
    for (int p = 0; p < 16; p++) acc += W[kp * 1024 + p * 64 + s];
    g_sw[z * 65536 + kp * 64 + s] = acc;
}

// ---------------------------------------------------------------------------
// g_sum[b, sg*64+s] = Σ_branches position-sums of branch outputs (with bias).
// grid (8, 16), 64 threads.
// ---------------------------------------------------------------------------
__global__ __launch_bounds__(64)
void gate_kernel(const float* __restrict__ wc,
                 const float* __restrict__ bh, const float* __restrict__ bw,
                 const float* __restrict__ bd, const float* __restrict__ bc)
{
    __shared__ float smh[1024], smw[1024], smd[1024], spc[1024];
    const int b = blockIdx.x, sg = blockIdx.y, s = threadIdx.x;

    for (int i = s; i < 1024; i += 64) {
        const int kk = i >> 6, s2 = i & 63;
        smh[i] = g_smh[(b * 16 + kk) * 1024 + sg * 64 + s2];
        float aw = 0.0f, ad = 0.0f, ap = 0.0f;
#pragma unroll
        for (int g = 0; g < 4; g++) {
            aw += g_smw4[((g * 8 + b) * 16 + kk) * 1024 + sg * 64 + s2];
            ad += g_smd4[((g * 8 + b) * 16 + kk) * 1024 + sg * 64 + s2];
            ap += g_sp4[(g * 8 + b) * 1024 + i];
        }
        smw[i] = aw; smd[i] = ad; spc[i] = ap;
    }
    __syncthreads();

    float acc = 0.0f;
    for (int k = 0; k < 1024; k++)
        acc += smh[k] * g_sw[k * 64 + s]
             + smw[k] * g_sw[65536 + k * 64 + s]
             + smd[k] * g_sw[131072 + k * 64 + s];
    for (int cp = 0; cp < 1024; cp++)
        acc += spc[cp] * wc[cp * 1024 + sg * 64 + s];

    float bsum = 0.0f;
#pragma unroll
    for (int p = 0; p < 16; p++)
        bsum += bh[p * 64 + s] + bw[p * 64 + s] + bd[p * 64 + s];
    acc += 256.0f * bsum + 4096.0f * bc[sg * 64 + s];

    g_sum[b * 1024 + sg * 64 + s] = acc;
}

// ---------------------------------------------------------------------------
// Gating MLP (unchanged from R12)
// ---------------------------------------------------------------------------
__global__ __launch_bounds__(1024)
void mlp1(const float* __restrict__ w1, const float* __restrict__ b1)
{
    __shared__ float sv[1024];
    __shared__ float red[4][256];
    const int b = blockIdx.x, tid = threadIdx.x;

    sv[tid] = g_sum[b * 1024 + tid] * (1.0f / 4096.0f);
    __syncthreads();

    const int o = tid & 255, part = tid >> 8;
    float acc = 0.0f;
    const float* wp = w1 + (part * 256) * 256 + o;
    const float* svp = sv + part * 256;
#pragma unroll 8
    for (int kk = 0; kk < 256; kk++) acc += svp[kk] * wp[kk * 256];
    red[part][o] = acc;
    __syncthreads();

    if (tid < 256) {
        float a = red[0][tid] + red[1][tid] + red[2][tid] + red[3][tid] + b1[tid];
        g_t[b * 256 + tid] = 0.5f * a * (1.0f + erff(a * 0.7071067811865476f));
    }
}

__global__ __launch_bounds__(256)
void mlp2(const float* __restrict__ w2, const float* __restrict__ b2)
{
    __shared__ float tt[256];
    __shared__ float zs[256];
    const int b = blockIdx.x, ny = blockIdx.y, tid = threadIdx.x;

    tt[tid] = g_t[b * 256 + tid];
    __syncthreads();

    const int n = ny * 256 + tid;
    float acc = b2[n];
#pragma unroll 8
    for (int k = 0; k < 256; k++) acc += tt[k] * w2[k * 4096 + n];
    zs[tid] = acc;
    __syncthreads();

    if (tid < 64) {
        const int c = ny * 64 + tid;
        const float v0 = zs[4*tid+0], v1 = zs[4*tid+1], v2 = zs[4*tid+2], v3 = zs[4*tid+3];
        const float mx = fmaxf(fmaxf(v0, v1), fmaxf(v2, v3));
        const float e0 = expf(v0-mx), e1 = expf(v1-mx), e2 = expf(v2-mx), e3 = expf(v3-mx);
        const float inv = 1.0f / (e0 + e1 + e2 + e3);
        g_a[0*8192 + b*1024 + c] = e0 * inv;
        g_a[1*8192 + b*1024 + c] = e1 * inv;
        g_a[2*8192 + b*1024 + c] = e2 * inv;
        g_a[3*8192 + b*1024 + c] = e3 * inv;
    }
}

// ---------------------------------------------------------------------------
extern "C" void kernel_launch(void* const* d_in, const int* in_sizes, int n_in,
                              void* d_out, int out_size)
{
    const float* x  = (const float*)d_in[0];
    const float* wh = (const float*)d_in[1];
    const float* bh = (const float*)d_in[2];
    const float* ww = (const float*)d_in[3];
    const float* bw = (const float*)d_in[4];
    const float* wd = (const float*)d_in[5];
    const float* bd = (const float*)d_in[6];
    const float* wc = (const float*)d_in[7];
    const float* bc = (const float*)d_in[8];
    const float* w1 = (const float*)d_in[9];
    const float* b1 = (const float*)d_in[10];
    const float* w2 = (const float*)d_in[11];
    const float* b2 = (const float*)d_in[12];
    const float* wp = (const float*)d_in[13];
    const float* bp = (const float*)d_in[14];
    float* out = (float*)d_out;

    // gating first (mean commutes with the GEMMs)
    psum_kernel<<<dim3(8, 8, 4), 128>>>(x);
    wred_kernel<<<dim3(1024, 3), 64>>>(wh, ww, wd);
    gate_kernel<<<dim3(8, 16), 64>>>(wc, bh, bw, bd, bc);
    mlp1<<<8, 1024>>>(w1, b1);
    mlp2<<<dim3(8, 16), 256>>>(w2, b2);

    dim3 grid(8, 256);
    // branch GEMMs with fused a_q-scale + accumulate into comb (g_h).
    // h must run first (initializes comb); w, d, c accumulate.
    gemm_mma<<<grid, 256>>>(x, wh, bh, 0, 64,     16384, 1024, 262144, nullptr);
    gemm_mma<<<grid, 256>>>(x, ww, bw, 1, 262144, 64,    1024, 16384,  nullptr);
    gemm_mma<<<grid, 256>>>(x, wd, bd, 2, 262144, 16384, 64,   1024,   nullptr);
    gemm_mma<<<grid, 256>>>(x, wc, bc, 3, 262144, 16384, 1024, 64,     nullptr);

    // final projection: plain GEMM on comb
    gemm_mma<<<grid, 256>>>(x, wp, bp, 4, 262144, 16384, 1024, 64, out);
}

// round 14
// speedup vs baseline: 2.5421x; 1.2399x over previous
#include <cuda_runtime.h>
#include <cuda_fp16.h>
#include <cstdint>
#include <math.h>

// ===========================================================================
// WeightedPermuteMLP — fp16 2-product ldmatrix+mma.sync, gating-first.
// A single fp16 (11-bit mantissa), B split hi/lo fp16:
//   D = A*Bh + A*Bl   (fp32 accum)  -> rel_err ~1.5e-4 (gate 1e-3)
// Gating computed BEFORE the GEMMs (mean commutes); branch epilogues apply
// a_q and accumulate into comb (g_h); final projection is a plain GEMM.
// ===========================================================================

#define NELEM 33554432

__device__ __align__(256) float g_h[NELEM];            // comb accumulator
__device__ __align__(256) float g_smh[8 * 16 * 1024];
__device__ __align__(256) float g_smw4[4 * 8 * 16 * 1024];
__device__ __align__(256) float g_smd4[4 * 8 * 16 * 1024];
__device__ __align__(256) float g_sp4[4 * 8 * 1024];
__device__ __align__(256) float g_sw[3 * 65536];
__device__ __align__(256) float g_sum[8 * 1024];
__device__ __align__(256) float g_t[8 * 256];
__device__ __align__(256) float g_a[4 * 8 * 1024];     // [q][b][chan]

__device__ __forceinline__ int row_base(int m, int s1, int s2, int s3) {
    return (m >> 12) * 4194304 + ((m >> 8) & 15) * s1 + ((m >> 4) & 15) * s2 + (m & 15) * s3;
}

__device__ __forceinline__ uint32_t s2u(const void* p) {
    uint32_t a;
    asm("{ .reg .u64 t; cvta.to.shared.u64 t, %1; cvt.u32.u64 %0, t; }" : "=r"(a) : "l"(p));
    return a;
}

// 8 fp32 -> 8 fp16 packed in one uint4
__device__ __forceinline__ void cvtA8(const float* f, uint4& v)
{
    uint32_t h[4];
#pragma unroll
    for (int j = 0; j < 4; j++) {
        __half2 p = __floats2half2_rn(f[2*j], f[2*j+1]);
        h[j] = *reinterpret_cast<uint32_t*>(&p);
    }
    v = make_uint4(h[0], h[1], h[2], h[3]);
}

// 8 fp32 -> fp16 hi/lo pairs packed in uint4 each
__device__ __forceinline__ void cvtB8(const float* f, uint4& hv, uint4& lv)
{
    uint32_t h[4], l[4];
#pragma unroll
    for (int j = 0; j < 4; j++) {
        const float x0 = f[2*j], x1 = f[2*j+1];
        const __half h0 = __float2half_rn(x0);
        const __half h1 = __float2half_rn(x1);
        __half2 hh = __halves2half2(h0, h1);
        __half2 ll = __halves2half2(
            __float2half_rn(x0 - __half2float(h0)),
            __float2half_rn(x1 - __half2float(h1)));
        h[j] = *reinterpret_cast<uint32_t*>(&hh);
        l[j] = *reinterpret_cast<uint32_t*>(&ll);
    }
    hv = make_uint4(h[0], h[1], h[2], h[3]);
    lv = make_uint4(l[0], l[1], l[2], l[3]);
}

#define LDSM4(R, ADDR) \
    asm volatile("ldmatrix.sync.aligned.m8n8.x4.shared.b16 {%0,%1,%2,%3}, [%4];" \
                 : "=r"((R)[0]), "=r"((R)[1]), "=r"((R)[2]), "=r"((R)[3]) : "r"(ADDR))
#define LDSM4T(R, ADDR) \
    asm volatile("ldmatrix.sync.aligned.m8n8.x4.trans.shared.b16 {%0,%1,%2,%3}, [%4];" \
                 : "=r"((R)[0]), "=r"((R)[1]), "=r"((R)[2]), "=r"((R)[3]) : "r"(ADDR))
#define MMA16816(D, A, B0, B1) \
    asm volatile("mma.sync.aligned.m16n8k16.row.col.f32.f16.f16.f32 " \
                 "{%0,%1,%2,%3}, {%4,%5,%6,%7}, {%8,%9}, {%0,%1,%2,%3};" \
                 : "+f"((D)[0]), "+f"((D)[1]), "+f"((D)[2]), "+f"((D)[3]) \
                 : "r"((A)[0]), "r"((A)[1]), "r"((A)[2]), "r"((A)[3]), "r"(B0), "r"(B1))

// ---------------------------------------------------------------------------
// GEMM: block 128x128, BK=16, 8 warps (2m x 4n), warp tile 64x32.
//  sel 0..3 (h,w,d,c): A gather from X; epilogue o = a_sel*(Z+bias), acc g_h.
//  sel 4: plain GEMM, A = g_h contiguous, write outF.
// Smem: 2 stages x 14848 B = 29696 B; 2 CTAs/SM.
// ---------------------------------------------------------------------------
#define KPAD2 24
#define NPAD 136
#define A_ELE (128 * KPAD2)              // 3072 fp16 (A single)
#define B_ELE (16 * NPAD)                // 2176 fp16
#define STG_ELE (A_ELE + 2 * B_ELE)      // 7424 fp16 = 14848 B
#define STG_BYTES (STG_ELE * 2)
#define OFF_BH A_ELE
#define OFF_BL (A_ELE + B_ELE)
#define EPAD 36

__global__ __launch_bounds__(256, 2)
void gemm_mma(const float* __restrict__ X, const float* __restrict__ Wm,
              const float* __restrict__ bias, int sel,
              int s1, int s2, int s3, int st, float* __restrict__ outF)
{
    __shared__ __align__(256) __half smem[2 * STG_ELE];

    const int tid = threadIdx.x;
    const int wid = tid >> 5;
    const int lane = tid & 31;
    const int bm = blockIdx.y * 128;
    const int bn = blockIdx.x * 128;

    const int r  = tid >> 1;
    const int lk = (tid & 1) * 8;
    const int abase = row_base(bm + r, s1, s2, s3) + lk;
    const int cbase = (bm + r) * 1024 + lk;
    const int sA = r * KPAD2 + lk;

    const int krow = tid >> 4;
    const int ncol = (tid & 15) * 8;
    const int bbase = krow * 1024 + bn + ncol;
    const int sB = krow * NPAD + ncol;

    float fa[8], fb[8];

#define GLOADA(T) do {                                                         \
    if (sel < 4) {                                                             \
        const float4* p_ = (const float4*)(X + abase + ((T) >> 2) * st + ((T) & 3) * 16); \
        float4 v0_ = p_[0], v1_ = p_[1];                                       \
        fa[0]=v0_.x; fa[1]=v0_.y; fa[2]=v0_.z; fa[3]=v0_.w;                    \
        fa[4]=v1_.x; fa[5]=v1_.y; fa[6]=v1_.z; fa[7]=v1_.w;                    \
    } else {                                                                   \
        const float4* p_ = (const float4*)(g_h + cbase + (T) * 16);            \
        float4 v0_ = p_[0], v1_ = p_[1];                                       \
        fa[0]=v0_.x; fa[1]=v0_.y; fa[2]=v0_.z; fa[3]=v0_.w;                    \
        fa[4]=v1_.x; fa[5]=v1_.y; fa[6]=v1_.z; fa[7]=v1_.w;                    \
    }                                                                          \
} while (0)

#define GLOADB(T) do {                                                         \
    const float4* p_ = (const float4*)(Wm + bbase + (T) * 16 * 1024);          \
    float4 v0_ = p_[0], v1_ = p_[1];                                           \
    fb[0]=v0_.x; fb[1]=v0_.y; fb[2]=v0_.z; fb[3]=v0_.w;                        \
    fb[4]=v1_.x; fb[5]=v1_.y; fb[6]=v1_.z; fb[7]=v1_.w;                        \
} while (0)

#define SCVT(STG) do {                                                         \
    __half* s0_ = smem + (STG) * STG_ELE;                                      \
    uint4 aV_, hB_, lB_;                                                       \
    cvtA8(fa, aV_);                                                            \
    cvtB8(fb, hB_, lB_);                                                       \
    *(uint4*)(s0_ + sA) = aV_;                                                 \
    *(uint4*)(s0_ + OFF_BH + sB) = hB_;                                        \
    *(uint4*)(s0_ + OFF_BL + sB) = lB_;                                        \
} while (0)

    const int wm = (wid >> 2) * 64;
    const int wn = (wid & 3) * 32;

    const uint32_t smem_u = s2u(smem);
    const int frow = ((lane >> 3) & 1) * 8 + (lane & 7);
    const int fcol = (lane >> 4) * 8;
    uint32_t aAd[4], bHi[2], bLo[2];
#pragma unroll
    for (int mt = 0; mt < 4; mt++)
        aAd[mt] = smem_u + (uint32_t)(((wm + mt*16 + frow) * KPAD2 + fcol) * 2);
#pragma unroll
    for (int g = 0; g < 2; g++) {
        const uint32_t off = (uint32_t)((frow * NPAD + wn + g*16 + fcol) * 2);
        bHi[g] = smem_u + OFF_BH * 2 + off;
        bLo[g] = smem_u + OFF_BL * 2 + off;
    }

    float acc[4][4][4];
#pragma unroll
    for (int mt = 0; mt < 4; mt++)
#pragma unroll
        for (int ng = 0; ng < 4; ng++)
#pragma unroll
            for (int q = 0; q < 4; q++) acc[mt][ng][q] = 0.0f;

    GLOADA(0);
    GLOADB(0);
    SCVT(0);
    __syncthreads();

    for (int t = 0; t < 64; t++) {
        if (t < 63) { GLOADA(t + 1); GLOADB(t + 1); }

        {
            const uint32_t sb = (uint32_t)(t & 1) * STG_BYTES;
            uint32_t a[4][4], bh[2][4], bl[2][4];
#pragma unroll
            for (int mt = 0; mt < 4; mt++) LDSM4(a[mt], aAd[mt] + sb);
            LDSM4T(bh[0], bHi[0] + sb);
            LDSM4T(bh[1], bHi[1] + sb);
            LDSM4T(bl[0], bLo[0] + sb);
            LDSM4T(bl[1], bLo[1] + sb);
            // P1: A * Bh
#pragma unroll
            for (int mt = 0; mt < 4; mt++)
#pragma unroll
                for (int ng = 0; ng < 4; ng++)
                    MMA16816(acc[mt][ng], a[mt], bh[ng>>1][(ng&1)*2], bh[ng>>1][(ng&1)*2+1]);
            // P2: A * Bl
#pragma unroll
            for (int mt = 0; mt < 4; mt++)
#pragma unroll
                for (int ng = 0; ng < 4; ng++)
                    MMA16816(acc[mt][ng], a[mt], bl[ng>>1][(ng&1)*2], bl[ng>>1][(ng&1)*2+1]);
        }

        if (t < 63) SCVT((t + 1) & 1);
        __syncthreads();
    }

    // ---- epilogue ----
    float* ep = (float*)smem + wid * (16 * EPAD);

    const int n0  = bn + wn;
    const int cc  = (lane & 7) * 4;
    const int offn = (n0 >> 6) * st + (n0 & 63) + cc;
    const int offc = n0 + cc;
    const float4 bv = *(const float4*)(bias + n0 + cc);

    const int er = lane >> 2;
    const int ec = 2 * (lane & 3);

    const int bq = bm >> 12;
    const int scol = (n0 & 63) + cc;
    const int by = blockIdx.y;
    const int sig0 = (by >> 1) & 15;
    const int sig1b = by * 8 + 4 * (wid >> 2);

#pragma unroll
    for (int mt = 0; mt < 4; mt++) {
#pragma unroll
        for (int ng = 0; ng < 4; ng++) {
            float2 v0, v1;
            v0.x = acc[mt][ng][0]; v0.y = acc[mt][ng][1];
            v1.x = acc[mt][ng][2]; v1.y = acc[mt][ng][3];
            *(float2*)(ep + er * EPAD + ng*8 + ec) = v0;
            *(float2*)(ep + (er + 8) * EPAD + ng*8 + ec) = v1;
        }
        __syncwarp();
        const int sig_mt = (sig1b + mt) & 15;
#pragma unroll
        for (int i = 0; i < 4; i++) {
            const int rr = i * 4 + (lane >> 3);
            const int m = bm + wm + mt * 16 + rr;
            const float* s = ep + rr * EPAD + cc;
            if (sel < 4) {
                const int ch = (sel == 0) ? (sig0 * 64 + scol)
                             : (sel == 1) ? (sig_mt * 64 + scol)
                             : (sel == 2) ? (rr * 64 + scol)
                             : offc;
                const float4 av = *(const float4*)(g_a + (sel << 13) + (bq << 10) + ch);
                const int adr = row_base(m, s1, s2, s3) + offn;
                float4 o;
                o.x = av.x * (s[0] + bv.x);
                o.y = av.y * (s[1] + bv.y);
                o.z = av.z * (s[2] + bv.z);
                o.w = av.w * (s[3] + bv.w);
                if (sel > 0) {
                    const float4 pv = *(const float4*)(g_h + adr);
                    o.x += pv.x; o.y += pv.y; o.z += pv.z; o.w += pv.w;
                }
                *(float4*)(g_h + adr) = o;
            } else {
                float4 o;
                o.x = s[0] + bv.x; o.y = s[1] + bv.y;
                o.z = s[2] + bv.z; o.w = s[3] + bv.w;
                *(float4*)(outF + m * 1024 + offc) = o;
            }
        }
        __syncwarp();
    }
#undef GLOADA
#undef GLOADB
#undef SCVT
}

// ---------------------------------------------------------------------------
// Partial sums of x (gating input); grid (8, 8, 4), 128 threads.
// ---------------------------------------------------------------------------
__global__ __launch_bounds__(128)
void psum_kernel(const float* __restrict__ X)
{
    const int b = blockIdx.x, cg = blockIdx.y, hg = blockIdx.z;
    const int c = cg * 128 + threadIdx.x;
    float sw[16], sd[16];
#pragma unroll
    for (int i = 0; i < 16; i++) { sw[i] = 0.0f; sd[i] = 0.0f; }
    float sp = 0.0f;
    const float* xb = X + (size_t)b * 4194304 + c;
    for (int hl = 0; hl < 4; hl++) {
        const int hh = hg * 4 + hl;
        float sh = 0.0f;
        const float* xh = xb + hh * 262144;
#pragma unroll
        for (int ww = 0; ww < 16; ww++)
#pragma unroll
            for (int dd = 0; dd < 16; dd++) {
                float v = xh[ww * 16384 + dd * 1024];
                sh += v; sw[ww] += v; sd[dd] += v;
            }
        g_smh[(b * 16 + hh) * 1024 + c] = sh;
        sp += sh;
    }
#pragma unroll
    for (int i = 0; i < 16; i++) {
        g_smw4[((hg * 8 + b) * 16 + i) * 1024 + c] = sw[i];
        g_smd4[((hg * 8 + b) * 16 + i) * 1024 + c] = sd[i];
    }
    g_sp4[(hg * 8 + b) * 1024 + c] = sp;
}

__global__ __launch_bounds__(64)
void wred_kernel(const float* __restrict__ w0, const float* __restrict__ w1,
                 const float* __restrict__ w2)
{
    const int kp = blockIdx.x, z = blockIdx.y, s = threadIdx.x;
    const float* W = (z == 0) ? w0 : (z == 1) ? w1 : w2;
    float acc = 0.0f;
#pragma unroll
    for (int p = 0; p < 16; p++) acc += W[kp * 1024 + p * 64 + s];
    g_sw[z * 65536 + kp * 64 + s] = acc;
}

__global__ __launch_bounds__(64)
void gate_kernel(const float* __restrict__ wc,
                 const float* __restrict__ bh, const float* __restrict__ bw,
                 const float* __restrict__ bd, const float* __restrict__ bc)
{
    __shared__ float smh[1024], smw[1024], smd[1024], spc[1024];
    const int b = blockIdx.x, sg = blockIdx.y, s = threadIdx.x;

    for (int i = s; i < 1024; i += 64) {
        const int kk = i >> 6, s2 = i & 63;
        smh[i] = g_smh[(b * 16 + kk) * 1024 + sg * 64 + s2];
        float aw = 0.0f, ad = 0.0f, ap = 0.0f;
#pragma unroll
        for (int g = 0; g < 4; g++) {
            aw += g_smw4[((g * 8 + b) * 16 + kk) * 1024 + sg * 64 + s2];
            ad += g_smd4[((g * 8 + b) * 16 + kk) * 1024 + sg * 64 + s2];
            ap += g_sp4[(g * 8 + b) * 1024 + i];
        }
        smw[i] = aw; smd[i] = ad; spc[i] = ap;
    }
    __syncthreads();

    float acc = 0.0f;
    for (int k = 0; k < 1024; k++)
        acc += smh[k] * g_sw[k * 64 + s]
             + smw[k] * g_sw[65536 + k * 64 + s]
             + smd[k] * g_sw[131072 + k * 64 + s];
    for (int cp = 0; cp < 1024; cp++)
        acc += spc[cp] * wc[cp * 1024 + sg * 64 + s];

    float bsum = 0.0f;
#pragma unroll
    for (int p = 0; p < 16; p++)
        bsum += bh[p * 64 + s] + bw[p * 64 + s] + bd[p * 64 + s];
    acc += 256.0f * bsum + 4096.0f * bc[sg * 64 + s];

    g_sum[b * 1024 + sg * 64 + s] = acc;
}

__global__ __launch_bounds__(1024)
void mlp1(const float* __restrict__ w1, const float* __restrict__ b1)
{
    __shared__ float sv[1024];
    __shared__ float red[4][256];
    const int b = blockIdx.x, tid = threadIdx.x;

    sv[tid] = g_sum[b * 1024 + tid] * (1.0f / 4096.0f);
    __syncthreads();

    const int o = tid & 255, part = tid >> 8;
    float acc = 0.0f;
    const float* wp = w1 + (part * 256) * 256 + o;
    const float* svp = sv + part * 256;
#pragma unroll 8
    for (int kk = 0; kk < 256; kk++) acc += svp[kk] * wp[kk * 256];
    red[part][o] = acc;
    __syncthreads();

    if (tid < 256) {
        float a = red[0][tid] + red[1][tid] + red[2][tid] + red[3][tid] + b1[tid];
        g_t[b * 256 + tid] = 0.5f * a * (1.0f + erff(a * 0.7071067811865476f));
    }
}

__global__ __launch_bounds__(256)
void mlp2(const float* __restrict__ w2, const float* __restrict__ b2)
{
    __shared__ float tt[256];
    __shared__ float zs[256];
    const int b = blockIdx.x, ny = blockIdx.y, tid = threadIdx.x;

    tt[tid] = g_t[b * 256 + tid];
    __syncthreads();

    const int n = ny * 256 + tid;
    float acc = b2[n];
#pragma unroll 8
    for (int k = 0; k < 256; k++) acc += tt[k] * w2[k * 4096 + n];
    zs[tid] = acc;
    __syncthreads();

    if (tid < 64) {
        const int c = ny * 64 + tid;
        const float v0 = zs[4*tid+0], v1 = zs[4*tid+1], v2 = zs[4*tid+2], v3 = zs[4*tid+3];
        const float mx = fmaxf(fmaxf(v0, v1), fmaxf(v2, v3));
        const float e0 = expf(v0-mx), e1 = expf(v1-mx), e2 = expf(v2-mx), e3 = expf(v3-mx);
        const float inv = 1.0f / (e0 + e1 + e2 + e3);
        g_a[0*8192 + b*1024 + c] = e0 * inv;
        g_a[1*8192 + b*1024 + c] = e1 * inv;
        g_a[2*8192 + b*1024 + c] = e2 * inv;
        g_a[3*8192 + b*1024 + c] = e3 * inv;
    }
}

// ---------------------------------------------------------------------------
extern "C" void kernel_launch(void* const* d_in, const int* in_sizes, int n_in,
                              void* d_out, int out_size)
{
    const float* x  = (const float*)d_in[0];
    const float* wh = (const float*)d_in[1];
    const float* bh = (const float*)d_in[2];
    const float* ww = (const float*)d_in[3];
    const float* bw = (const float*)d_in[4];
    const float* wd = (const float*)d_in[5];
    const float* bd = (const float*)d_in[6];
    const float* wc = (const float*)d_in[7];
    const float* bc = (const float*)d_in[8];
    const float* w1 = (const float*)d_in[9];
    const float* b1 = (const float*)d_in[10];
    const float* w2 = (const float*)d_in[11];
    const float* b2 = (const float*)d_in[12];
    const float* wp = (const float*)d_in[13];
    const float* bp = (const float*)d_in[14];
    float* out = (float*)d_out;

    // gating first (mean commutes with the GEMMs)
    psum_kernel<<<dim3(8, 8, 4), 128>>>(x);
    wred_kernel<<<dim3(1024, 3), 64>>>(wh, ww, wd);
    gate_kernel<<<dim3(8, 16), 64>>>(wc, bh, bw, bd, bc);
    mlp1<<<8, 1024>>>(w1, b1);
    mlp2<<<dim3(8, 16), 256>>>(w2, b2);

    dim3 grid(8, 256);
    // branch GEMMs with fused a_q-scale + accumulate into comb (g_h);
    // h first (initializes comb), then w, d, c accumulate.
    gemm_mma<<<grid, 256>>>(x, wh, bh, 0, 64,     16384, 1024, 262144, nullptr);
    gemm_mma<<<grid, 256>>>(x, ww, bw, 1, 262144, 64,    1024, 16384,  nullptr);
    gemm_mma<<<grid, 256>>>(x, wd, bd, 2, 262144, 16384, 64,   1024,   nullptr);
    gemm_mma<<<grid, 256>>>(x, wc, bc, 3, 262144, 16384, 1024, 64,     nullptr);

    // final projection: plain GEMM on comb
    gemm_mma<<<grid, 256>>>(x, wp, bp, 4, 262144, 16384, 1024, 64, out);
}

// round 15
// speedup vs baseline: 2.8091x; 1.1050x over previous
#include <cuda_runtime.h>
#include <cuda_fp16.h>
#include <cstdint>
#include <math.h>

// ===========================================================================
// WeightedPermuteMLP — fp16 single-product ldmatrix+mma.sync, gating-first.
// A and B both single fp16 (fp32 accum): rel_err ~4.5e-4 (gate 1e-3).
// Gating computed BEFORE the GEMMs (mean commutes); branch epilogues apply
// a_q and accumulate into comb (g_h); final projection is a plain GEMM.
// ===========================================================================

#define NELEM 33554432

__device__ __align__(256) float g_h[NELEM];            // comb accumulator
__device__ __align__(256) float g_smh[8 * 16 * 1024];
__device__ __align__(256) float g_smw4[4 * 8 * 16 * 1024];
__device__ __align__(256) float g_smd4[4 * 8 * 16 * 1024];
__device__ __align__(256) float g_sp4[4 * 8 * 1024];
__device__ __align__(256) float g_sw[3 * 65536];
__device__ __align__(256) float g_sum[8 * 1024];
__device__ __align__(256) float g_t[8 * 256];
__device__ __align__(256) float g_a[4 * 8 * 1024];     // [q][b][chan]

__device__ __forceinline__ int row_base(int m, int s1, int s2, int s3) {
    return (m >> 12) * 4194304 + ((m >> 8) & 15) * s1 + ((m >> 4) & 15) * s2 + (m & 15) * s3;
}

__device__ __forceinline__ uint32_t s2u(const void* p) {
    uint32_t a;
    asm("{ .reg .u64 t; cvta.to.shared.u64 t, %1; cvt.u32.u64 %0, t; }" : "=r"(a) : "l"(p));
    return a;
}

// 8 fp32 -> 8 fp16 packed in one uint4
__device__ __forceinline__ void cvt8(const float* f, uint4& v)
{
    uint32_t h[4];
#pragma unroll
    for (int j = 0; j < 4; j++) {
        __half2 p = __floats2half2_rn(f[2*j], f[2*j+1]);
        h[j] = *reinterpret_cast<uint32_t*>(&p);
    }
    v = make_uint4(h[0], h[1], h[2], h[3]);
}

#define LDSM4(R, ADDR) \
    asm volatile("ldmatrix.sync.aligned.m8n8.x4.shared.b16 {%0,%1,%2,%3}, [%4];" \
                 : "=r"((R)[0]), "=r"((R)[1]), "=r"((R)[2]), "=r"((R)[3]) : "r"(ADDR))
#define LDSM4T(R, ADDR) \
    asm volatile("ldmatrix.sync.aligned.m8n8.x4.trans.shared.b16 {%0,%1,%2,%3}, [%4];" \
                 : "=r"((R)[0]), "=r"((R)[1]), "=r"((R)[2]), "=r"((R)[3]) : "r"(ADDR))
#define MMA16816(D, A, B0, B1) \
    asm volatile("mma.sync.aligned.m16n8k16.row.col.f32.f16.f16.f32 " \
                 "{%0,%1,%2,%3}, {%4,%5,%6,%7}, {%8,%9}, {%0,%1,%2,%3};" \
                 : "+f"((D)[0]), "+f"((D)[1]), "+f"((D)[2]), "+f"((D)[3]) \
                 : "r"((A)[0]), "r"((A)[1]), "r"((A)[2]), "r"((A)[3]), "r"(B0), "r"(B1))

// ---------------------------------------------------------------------------
// GEMM: block 128x128, BK=16, 8 warps (2m x 4n), warp tile 64x32.
//  sel 0..3 (h,w,d,c): A gather from X; epilogue o = a_sel*(Z+bias), acc g_h.
//  sel 4: plain GEMM, A = g_h contiguous, write outF.
// Smem: 2 stages x 10496 B = 20992 B; 2 CTAs/SM.
// ---------------------------------------------------------------------------
#define KPAD2 24
#define NPAD 136
#define A_ELE (128 * KPAD2)              // 3072 fp16
#define B_ELE (16 * NPAD)                // 2176 fp16
#define STG_ELE (A_ELE + B_ELE)          // 5248 fp16 = 10496 B
#define STG_BYTES (STG_ELE * 2)
#define OFF_BH A_ELE
#define EPAD 36

__global__ __launch_bounds__(256, 2)
void gemm_mma(const float* __restrict__ X, const float* __restrict__ Wm,
              const float* __restrict__ bias, int sel,
              int s1, int s2, int s3, int st, float* __restrict__ outF)
{
    __shared__ __align__(256) __half smem[2 * STG_ELE + 2048];  // +slack for epilogue

    const int tid = threadIdx.x;
    const int wid = tid >> 5;
    const int lane = tid & 31;
    const int bm = blockIdx.y * 128;
    const int bn = blockIdx.x * 128;

    const int r  = tid >> 1;
    const int lk = (tid & 1) * 8;
    const int abase = row_base(bm + r, s1, s2, s3) + lk;
    const int cbase = (bm + r) * 1024 + lk;
    const int sA = r * KPAD2 + lk;

    const int krow = tid >> 4;
    const int ncol = (tid & 15) * 8;
    const int bbase = krow * 1024 + bn + ncol;
    const int sB = krow * NPAD + ncol;

    float fa[8], fb[8];

#define GLOADA(T) do {                                                         \
    if (sel < 4) {                                                             \
        const float4* p_ = (const float4*)(X + abase + ((T) >> 2) * st + ((T) & 3) * 16); \
        float4 v0_ = p_[0], v1_ = p_[1];                                       \
        fa[0]=v0_.x; fa[1]=v0_.y; fa[2]=v0_.z; fa[3]=v0_.w;                    \
        fa[4]=v1_.x; fa[5]=v1_.y; fa[6]=v1_.z; fa[7]=v1_.w;                    \
    } else {                                                                   \
        const float4* p_ = (const float4*)(g_h + cbase + (T) * 16);            \
        float4 v0_ = p_[0], v1_ = p_[1];                                       \
        fa[0]=v0_.x; fa[1]=v0_.y; fa[2]=v0_.z; fa[3]=v0_.w;                    \
        fa[4]=v1_.x; fa[5]=v1_.y; fa[6]=v1_.z; fa[7]=v1_.w;                    \
    }                                                                          \
} while (0)

#define GLOADB(T) do {                                                         \
    const float4* p_ = (const float4*)(Wm + bbase + (T) * 16 * 1024);          \
    float4 v0_ = p_[0], v1_ = p_[1];                                           \
    fb[0]=v0_.x; fb[1]=v0_.y; fb[2]=v0_.z; fb[3]=v0_.w;                        \
    fb[4]=v1_.x; fb[5]=v1_.y; fb[6]=v1_.z; fb[7]=v1_.w;                        \
} while (0)

#define SCVT(STG) do {                                                         \
    __half* s0_ = smem + (STG) * STG_ELE;                                      \
    uint4 aV_, bV_;                                                            \
    cvt8(fa, aV_);                                                             \
    cvt8(fb, bV_);                                                             \
    *(uint4*)(s0_ + sA) = aV_;                                                 \
    *(uint4*)(s0_ + OFF_BH + sB) = bV_;                                        \
} while (0)

    const int wm = (wid >> 2) * 64;
    const int wn = (wid & 3) * 32;

    const uint32_t smem_u = s2u(smem);
    const int frow = ((lane >> 3) & 1) * 8 + (lane & 7);
    const int fcol = (lane >> 4) * 8;
    uint32_t aAd[4], bAd[2];
#pragma unroll
    for (int mt = 0; mt < 4; mt++)
        aAd[mt] = smem_u + (uint32_t)(((wm + mt*16 + frow) * KPAD2 + fcol) * 2);
#pragma unroll
    for (int g = 0; g < 2; g++)
        bAd[g] = smem_u + OFF_BH * 2
               + (uint32_t)((frow * NPAD + wn + g*16 + fcol) * 2);

    float acc[4][4][4];
#pragma unroll
    for (int mt = 0; mt < 4; mt++)
#pragma unroll
        for (int ng = 0; ng < 4; ng++)
#pragma unroll
            for (int q = 0; q < 4; q++) acc[mt][ng][q] = 0.0f;

    GLOADA(0);
    GLOADB(0);
    SCVT(0);
    __syncthreads();

    for (int t = 0; t < 64; t++) {
        if (t < 63) { GLOADA(t + 1); GLOADB(t + 1); }

        {
            const uint32_t sb = (uint32_t)(t & 1) * STG_BYTES;
            uint32_t a[4][4], bh[2][4];
#pragma unroll
            for (int mt = 0; mt < 4; mt++) LDSM4(a[mt], aAd[mt] + sb);
            LDSM4T(bh[0], bAd[0] + sb);
            LDSM4T(bh[1], bAd[1] + sb);
#pragma unroll
            for (int mt = 0; mt < 4; mt++)
#pragma unroll
                for (int ng = 0; ng < 4; ng++)
                    MMA16816(acc[mt][ng], a[mt], bh[ng>>1][(ng&1)*2], bh[ng>>1][(ng&1)*2+1]);
        }

        if (t < 63) SCVT((t + 1) & 1);
        __syncthreads();
    }

    // ---- epilogue ----
    float* ep = (float*)smem + wid * (16 * EPAD);

    const int n0  = bn + wn;
    const int cc  = (lane & 7) * 4;
    const int offn = (n0 >> 6) * st + (n0 & 63) + cc;
    const int offc = n0 + cc;
    const float4 bv = *(const float4*)(bias + n0 + cc);

    const int er = lane >> 2;
    const int ec = 2 * (lane & 3);

    const int bq = bm >> 12;
    const int scol = (n0 & 63) + cc;
    const int by = blockIdx.y;
    const int sig0 = (by >> 1) & 15;
    const int sig1b = by * 8 + 4 * (wid >> 2);

#pragma unroll
    for (int mt = 0; mt < 4; mt++) {
#pragma unroll
        for (int ng = 0; ng < 4; ng++) {
            float2 v0, v1;
            v0.x = acc[mt][ng][0]; v0.y = acc[mt][ng][1];
            v1.x = acc[mt][ng][2]; v1.y = acc[mt][ng][3];
            *(float2*)(ep + er * EPAD + ng*8 + ec) = v0;
            *(float2*)(ep + (er + 8) * EPAD + ng*8 + ec) = v1;
        }
        __syncwarp();
        const int sig_mt = (sig1b + mt) & 15;
#pragma unroll
        for (int i = 0; i < 4; i++) {
            const int rr = i * 4 + (lane >> 3);
            const int m = bm + wm + mt * 16 + rr;
            const float* s = ep + rr * EPAD + cc;
            if (sel < 4) {
                const int ch = (sel == 0) ? (sig0 * 64 + scol)
                             : (sel == 1) ? (sig_mt * 64 + scol)
                             : (sel == 2) ? (rr * 64 + scol)
                             : offc;
                const float4 av = *(const float4*)(g_a + (sel << 13) + (bq << 10) + ch);
                const int adr = row_base(m, s1, s2, s3) + offn;
                float4 o;
                o.x = av.x * (s[0] + bv.x);
                o.y = av.y * (s[1] + bv.y);
                o.z = av.z * (s[2] + bv.z);
                o.w = av.w * (s[3] + bv.w);
                if (sel > 0) {
                    const float4 pv = *(const float4*)(g_h + adr);
                    o.x += pv.x; o.y += pv.y; o.z += pv.z; o.w += pv.w;
                }
                *(float4*)(g_h + adr) = o;
            } else {
                float4 o;
                o.x = s[0] + bv.x; o.y = s[1] + bv.y;
                o.z = s[2] + bv.z; o.w = s[3] + bv.w;
                *(float4*)(outF + m * 1024 + offc) = o;
            }
        }
        __syncwarp();
    }
#undef GLOADA
#undef GLOADB
#undef SCVT
}

// ---------------------------------------------------------------------------
// Partial sums of x (gating input); grid (8, 8, 4), 128 threads.
// ---------------------------------------------------------------------------
__global__ __launch_bounds__(128)
void psum_kernel(const float* __restrict__ X)
{
    const int b = blockIdx.x, cg = blockIdx.y, hg = blockIdx.z;
    const int c = cg * 128 + threadIdx.x;
    float sw[16], sd[16];
#pragma unroll
    for (int i = 0; i < 16; i++) { sw[i] = 0.0f; sd[i] = 0.0f; }
    float sp = 0.0f;
    const float* xb = X + (size_t)b * 4194304 + c;
    for (int hl = 0; hl < 4; hl++) {
        const int hh = hg * 4 + hl;
        float sh = 0.0f;
        const float* xh = xb + hh * 262144;
#pragma unroll
        for (int ww = 0; ww < 16; ww++)
#pragma unroll
            for (int dd = 0; dd < 16; dd++) {
                float v = xh[ww * 16384 + dd * 1024];
                sh += v; sw[ww] += v; sd[dd] += v;
            }
        g_smh[(b * 16 + hh) * 1024 + c] = sh;
        sp += sh;
    }
#pragma unroll
    for (int i = 0; i < 16; i++) {
        g_smw4[((hg * 8 + b) * 16 + i) * 1024 + c] = sw[i];
        g_smd4[((hg * 8 + b) * 16 + i) * 1024 + c] = sd[i];
    }
    g_sp4[(hg * 8 + b) * 1024 + c] = sp;
}

__global__ __launch_bounds__(64)
void wred_kernel(const float* __restrict__ w0, const float* __restrict__ w1,
                 const float* __restrict__ w2)
{
    const int kp = blockIdx.x, z = blockIdx.y, s = threadIdx.x;
    const float* W = (z == 0) ? w0 : (z == 1) ? w1 : w2;
    float acc = 0.0f;
#pragma unroll
    for (int p = 0; p < 16; p++) acc += W[kp * 1024 + p * 64 + s];
    g_sw[z * 65536 + kp * 64 + s] = acc;
}

__global__ __launch_bounds__(64)
void gate_kernel(const float* __restrict__ wc,
                 const float* __restrict__ bh, const float* __restrict__ bw,
                 const float* __restrict__ bd, const float* __restrict__ bc)
{
    __shared__ float smh[1024], smw[1024], smd[1024], spc[1024];
    const int b = blockIdx.x, sg = blockIdx.y, s = threadIdx.x;

    for (int i = s; i < 1024; i += 64) {
        const int kk = i >> 6, s2 = i & 63;
        smh[i] = g_smh[(b * 16 + kk) * 1024 + sg * 64 + s2];
        float aw = 0.0f, ad = 0.0f, ap = 0.0f;
#pragma unroll
        for (int g = 0; g < 4; g++) {
            aw += g_smw4[((g * 8 + b) * 16 + kk) * 1024 + sg * 64 + s2];
            ad += g_smd4[((g * 8 + b) * 16 + kk) * 1024 + sg * 64 + s2];
            ap += g_sp4[(g * 8 + b) * 1024 + i];
        }
        smw[i] = aw; smd[i] = ad; spc[i] = ap;
    }
    __syncthreads();

    float acc = 0.0f;
    for (int k = 0; k < 1024; k++)
        acc += smh[k] * g_sw[k * 64 + s]
             + smw[k] * g_sw[65536 + k * 64 + s]
             + smd[k] * g_sw[131072 + k * 64 + s];
    for (int cp = 0; cp < 1024; cp++)
        acc += spc[cp] * wc[cp * 1024 + sg * 64 + s];

    float bsum = 0.0f;
#pragma unroll
    for (int p = 0; p < 16; p++)
        bsum += bh[p * 64 + s] + bw[p * 64 + s] + bd[p * 64 + s];
    acc += 256.0f * bsum + 4096.0f * bc[sg * 64 + s];

    g_sum[b * 1024 + sg * 64 + s] = acc;
}

__global__ __launch_bounds__(1024)
void mlp1(const float* __restrict__ w1, const float* __restrict__ b1)
{
    __shared__ float sv[1024];
    __shared__ float red[4][256];
    const int b = blockIdx.x, tid = threadIdx.x;

    sv[tid] = g_sum[b * 1024 + tid] * (1.0f / 4096.0f);
    __syncthreads();

    const int o = tid & 255, part = tid >> 8;
    float acc = 0.0f;
    const float* wp = w1 + (part * 256) * 256 + o;
    const float* svp = sv + part * 256;
#pragma unroll 8
    for (int kk = 0; kk < 256; kk++) acc += svp[kk] * wp[kk * 256];
    red[part][o] = acc;
    __syncthreads();

    if (tid < 256) {
        float a = red[0][tid] + red[1][tid] + red[2][tid] + red[3][tid] + b1[tid];
        g_t[b * 256 + tid] = 0.5f * a * (1.0f + erff(a * 0.7071067811865476f));
    }
}

__global__ __launch_bounds__(256)
void mlp2(const float* __restrict__ w2, const float* __restrict__ b2)
{
    __shared__ float tt[256];
    __shared__ float zs[256];
    const int b = blockIdx.x, ny = blockIdx.y, tid = threadIdx.x;

    tt[tid] = g_t[b * 256 + tid];
    __syncthreads();

    const int n = ny * 256 + tid;
    float acc = b2[n];
#pragma unroll 8
    for (int k = 0; k < 256; k++) acc += tt[k] * w2[k * 4096 + n];
    zs[tid] = acc;
    __syncthreads();

    if (tid < 64) {
        const int c = ny * 64 + tid;
        const float v0 = zs[4*tid+0], v1 = zs[4*tid+1], v2 = zs[4*tid+2], v3 = zs[4*tid+3];
        const float mx = fmaxf(fmaxf(v0, v1), fmaxf(v2, v3));
        const float e0 = expf(v0-mx), e1 = expf(v1-mx), e2 = expf(v2-mx), e3 = expf(v3-mx);
        const float inv = 1.0f / (e0 + e1 + e2 + e3);
        g_a[0*8192 + b*1024 + c] = e0 * inv;
        g_a[1*8192 + b*1024 + c] = e1 * inv;
        g_a[2*8192 + b*1024 + c] = e2 * inv;
        g_a[3*8192 + b*1024 + c] = e3 * inv;
    }
}

// ---------------------------------------------------------------------------
extern "C" void kernel_launch(void* const* d_in, const int* in_sizes, int n_in,
                              void* d_out, int out_size)
{
    const float* x  = (const float*)d_in[0];
    const float* wh = (const float*)d_in[1];
    const float* bh = (const float*)d_in[2];
    const float* ww = (const float*)d_in[3];
    const float* bw = (const float*)d_in[4];
    const float* wd = (const float*)d_in[5];
    const float* bd = (const float*)d_in[6];
    const float* wc = (const float*)d_in[7];
    const float* bc = (const float*)d_in[8];
    const float* w1 = (const float*)d_in[9];
    const float* b1 = (const float*)d_in[10];
    const float* w2 = (const float*)d_in[11];
    const float* b2 = (const float*)d_in[12];
    const float* wp = (const float*)d_in[13];
    const float* bp = (const float*)d_in[14];
    float* out = (float*)d_out;

    // gating first (mean commutes with the GEMMs)
    psum_kernel<<<dim3(8, 8, 4), 128>>>(x);
    wred_kernel<<<dim3(1024, 3), 64>>>(wh, ww, wd);
    gate_kernel<<<dim3(8, 16), 64>>>(wc, bh, bw, bd, bc);
    mlp1<<<8, 1024>>>(w1, b1);
    mlp2<<<dim3(8, 16), 256>>>(w2, b2);

    dim3 grid(8, 256);
    // branch GEMMs with fused a_q-scale + accumulate into comb (g_h);
    // h first (initializes comb), then w, d, c accumulate.
    gemm_mma<<<grid, 256>>>(x, wh, bh, 0, 64,     16384, 1024, 262144, nullptr);
    gemm_mma<<<grid, 256>>>(x, ww, bw, 1, 262144, 64,    1024, 16384,  nullptr);
    gemm_mma<<<grid, 256>>>(x, wd, bd, 2, 262144, 16384, 64,   1024,   nullptr);
    gemm_mma<<<grid, 256>>>(x, wc, bc, 3, 262144, 16384, 1024, 64,     nullptr);

    // final projection: plain GEMM on comb
    gemm_mma<<<grid, 256>>>(x, wp, bp, 4, 262144, 16384, 1024, 64, out);
}

// round 16
// speedup vs baseline: 2.9729x; 1.0583x over previous
#include <cuda_runtime.h>
#include <cuda_fp16.h>
#include <cstdint>
#include <math.h>

// ===========================================================================
// WeightedPermuteMLP — fp16 single-product ldmatrix+mma.sync, gating-first.
// R16: 128x256 block tiles (512 thr, 16 warps), fp16 comb buffer.
// D = A*B (both fp16, fp32 accum): rel_err ~5e-4 (gate 1e-3).
// ===========================================================================

#define NELEM 33554432

__device__ __align__(256) __half g_hc[NELEM];          // comb accumulator (fp16)
__device__ __align__(256) float g_smh[8 * 16 * 1024];
__device__ __align__(256) float g_smw4[4 * 8 * 16 * 1024];
__device__ __align__(256) float g_smd4[4 * 8 * 16 * 1024];
__device__ __align__(256) float g_sp4[4 * 8 * 1024];
__device__ __align__(256) float g_sw[3 * 65536];
__device__ __align__(256) float g_sum[8 * 1024];
__device__ __align__(256) float g_t[8 * 256];
__device__ __align__(256) float g_a[4 * 8 * 1024];     // [q][b][chan]

__device__ __forceinline__ int row_base(int m, int s1, int s2, int s3) {
    return (m >> 12) * 4194304 + ((m >> 8) & 15) * s1 + ((m >> 4) & 15) * s2 + (m & 15) * s3;
}

__device__ __forceinline__ uint32_t s2u(const void* p) {
    uint32_t a;
    asm("{ .reg .u64 t; cvta.to.shared.u64 t, %1; cvt.u32.u64 %0, t; }" : "=r"(a) : "l"(p));
    return a;
}

__device__ __forceinline__ uint2 cvt4(const float* f)
{
    __half2 p0 = __floats2half2_rn(f[0], f[1]);
    __half2 p1 = __floats2half2_rn(f[2], f[3]);
    return make_uint2(*reinterpret_cast<uint32_t*>(&p0), *reinterpret_cast<uint32_t*>(&p1));
}
__device__ __forceinline__ uint4 cvt8(const float* f)
{
    uint32_t h[4];
#pragma unroll
    for (int j = 0; j < 4; j++) {
        __half2 p = __floats2half2_rn(f[2*j], f[2*j+1]);
        h[j] = *reinterpret_cast<uint32_t*>(&p);
    }
    return make_uint4(h[0], h[1], h[2], h[3]);
}

#define LDSM4(R, ADDR) \
    asm volatile("ldmatrix.sync.aligned.m8n8.x4.shared.b16 {%0,%1,%2,%3}, [%4];" \
                 : "=r"((R)[0]), "=r"((R)[1]), "=r"((R)[2]), "=r"((R)[3]) : "r"(ADDR))
#define LDSM4T(R, ADDR) \
    asm volatile("ldmatrix.sync.aligned.m8n8.x4.trans.shared.b16 {%0,%1,%2,%3}, [%4];" \
                 : "=r"((R)[0]), "=r"((R)[1]), "=r"((R)[2]), "=r"((R)[3]) : "r"(ADDR))
#define MMA16816(D, A, B0, B1) \
    asm volatile("mma.sync.aligned.m16n8k16.row.col.f32.f16.f16.f32 " \
                 "{%0,%1,%2,%3}, {%4,%5,%6,%7}, {%8,%9}, {%0,%1,%2,%3};" \
                 : "+f"((D)[0]), "+f"((D)[1]), "+f"((D)[2]), "+f"((D)[3]) \
                 : "r"((A)[0]), "r"((A)[1]), "r"((A)[2]), "r"((A)[3]), "r"(B0), "r"(B1))

// ---------------------------------------------------------------------------
// GEMM: block 128x256, BK=16, 512 thr, 16 warps (2m x 8n), warp tile 64x32.
//  sel 0..3 (h,w,d,c): A gather from X; epilogue o = a_sel*(Z+bias), RMW g_hc.
//  sel 4: plain GEMM, A = g_hc (fp16) contiguous, write outF (fp32).
// ---------------------------------------------------------------------------
#define KPAD2 24
#define NPAD 264
#define A_ELE (128 * KPAD2)              // 3072 fp16
#define B_ELE (16 * NPAD)                // 4224 fp16
#define STG_ELE (A_ELE + B_ELE)          // 7296 fp16
#define STG_BYTES (STG_ELE * 2)
#define OFF_B A_ELE
#define EPAD 36
// smem: max(2 stages = 14592 halves, epilogue 16 warps*576 floats = 18432 halves)
#define SMEM_ELE 18560

__global__ __launch_bounds__(512, 1)
void gemm_mma(const float* __restrict__ X, const float* __restrict__ Wm,
              const float* __restrict__ bias, int sel,
              int s1, int s2, int s3, int st, float* __restrict__ outF)
{
    __shared__ __align__(256) __half smem[SMEM_ELE];

    const int tid = threadIdx.x;
    const int wid = tid >> 5;
    const int lane = tid & 31;
    const int bm = blockIdx.y * 128;
    const int bn = blockIdx.x * 256;

    // ---- A loader: thread -> (row r = tid>>2, lk = (tid&3)*4) ----
    const int r  = tid >> 2;
    const int lk = (tid & 3) * 4;
    const int abase = row_base(bm + r, s1, s2, s3) + lk;
    const int cbase = (bm + r) * 1024 + lk;
    const int sA = r * KPAD2 + lk;

    // ---- B loader: thread -> (krow = tid>>5, ncol = (tid&31)*8) ----
    const int krow = tid >> 5;
    const int ncol = (tid & 31) * 8;
    const int bbase = krow * 1024 + bn + ncol;
    const int sB = krow * NPAD + ncol;

    float fa[4], fb[8];
    uint2 faH;   // sel==4 path (already fp16)

#define GLOADA(T) do {                                                         \
    if (sel < 4) {                                                             \
        const float4 v_ = *(const float4*)(X + abase + ((T) >> 2) * st + ((T) & 3) * 16); \
        fa[0]=v_.x; fa[1]=v_.y; fa[2]=v_.z; fa[3]=v_.w;                        \
    } else {                                                                   \
        faH = *(const uint2*)(g_hc + cbase + (T) * 16);                        \
    }                                                                          \
} while (0)

#define GLOADB(T) do {                                                         \
    const float4* p_ = (const float4*)(Wm + bbase + (T) * 16 * 1024);          \
    float4 v0_ = p_[0], v1_ = p_[1];                                           \
    fb[0]=v0_.x; fb[1]=v0_.y; fb[2]=v0_.z; fb[3]=v0_.w;                        \
    fb[4]=v1_.x; fb[5]=v1_.y; fb[6]=v1_.z; fb[7]=v1_.w;                        \
} while (0)

#define SCVT(STG) do {                                                         \
    __half* s0_ = smem + (STG) * STG_ELE;                                      \
    *(uint2*)(s0_ + sA) = (sel < 4) ? cvt4(fa) : faH;                          \
    *(uint4*)(s0_ + OFF_B + sB) = cvt8(fb);                                    \
} while (0)

    // ---- warp tiling: 2(m) x 8(n); warp tile 64x32 ----
    const int widm = wid >> 3;
    const int wm = widm * 64;
    const int wn = (wid & 7) * 32;

    const uint32_t smem_u = s2u(smem);
    const int frow = ((lane >> 3) & 1) * 8 + (lane & 7);
    const int fcol = (lane >> 4) * 8;
    uint32_t aAd[4], bAd[2];
#pragma unroll
    for (int mt = 0; mt < 4; mt++)
        aAd[mt] = smem_u + (uint32_t)(((wm + mt*16 + frow) * KPAD2 + fcol) * 2);
#pragma unroll
    for (int g = 0; g < 2; g++)
        bAd[g] = smem_u + OFF_B * 2
               + (uint32_t)((frow * NPAD + wn + g*16 + fcol) * 2);

    float acc[4][4][4];
#pragma unroll
    for (int mt = 0; mt < 4; mt++)
#pragma unroll
        for (int ng = 0; ng < 4; ng++)
#pragma unroll
            for (int q = 0; q < 4; q++) acc[mt][ng][q] = 0.0f;

    GLOADA(0);
    GLOADB(0);
    SCVT(0);
    __syncthreads();

    for (int t = 0; t < 64; t++) {
        if (t < 63) { GLOADA(t + 1); GLOADB(t + 1); }

        {
            const uint32_t sb = (uint32_t)(t & 1) * STG_BYTES;
            uint32_t a[4][4], bh[2][4];
#pragma unroll
            for (int mt = 0; mt < 4; mt++) LDSM4(a[mt], aAd[mt] + sb);
            LDSM4T(bh[0], bAd[0] + sb);
            LDSM4T(bh[1], bAd[1] + sb);
#pragma unroll
            for (int mt = 0; mt < 4; mt++)
#pragma unroll
                for (int ng = 0; ng < 4; ng++)
                    MMA16816(acc[mt][ng], a[mt], bh[ng>>1][(ng&1)*2], bh[ng>>1][(ng&1)*2+1]);
        }

        if (t < 63) SCVT((t + 1) & 1);
        __syncthreads();
    }

    // ---- epilogue ----
    float* ep = (float*)smem + wid * (16 * EPAD);

    const int n0  = bn + wn;
    const int cc  = (lane & 7) * 4;
    const int offn = (n0 >> 6) * st + (n0 & 63) + cc;
    const int offc = n0 + cc;
    const float4 bv = *(const float4*)(bias + n0 + cc);

    const int er = lane >> 2;
    const int ec = 2 * (lane & 3);

    const int bq = bm >> 12;
    const int scol = (n0 & 63) + cc;
    const int by = blockIdx.y;
    const int sig0 = (by >> 1) & 15;
    const int sig1b = by * 8 + 4 * widm;

#pragma unroll
    for (int mt = 0; mt < 4; mt++) {
#pragma unroll
        for (int ng = 0; ng < 4; ng++) {
            float2 v0, v1;
            v0.x = acc[mt][ng][0]; v0.y = acc[mt][ng][1];
            v1.x = acc[mt][ng][2]; v1.y = acc[mt][ng][3];
            *(float2*)(ep + er * EPAD + ng*8 + ec) = v0;
            *(float2*)(ep + (er + 8) * EPAD + ng*8 + ec) = v1;
        }
        __syncwarp();
        const int sig_mt = (sig1b + mt) & 15;
#pragma unroll
        for (int i = 0; i < 4; i++) {
            const int rr = i * 4 + (lane >> 3);
            const int m = bm + wm + mt * 16 + rr;
            const float* s = ep + rr * EPAD + cc;
            if (sel < 4) {
                const int ch = (sel == 0) ? (sig0 * 64 + scol)
                             : (sel == 1) ? (sig_mt * 64 + scol)
                             : (sel == 2) ? (rr * 64 + scol)
                             : offc;
                const float4 av = *(const float4*)(g_a + (sel << 13) + (bq << 10) + ch);
                const int adr = row_base(m, s1, s2, s3) + offn;
                float o0 = av.x * (s[0] + bv.x);
                float o1 = av.y * (s[1] + bv.y);
                float o2 = av.z * (s[2] + bv.z);
                float o3 = av.w * (s[3] + bv.w);
                if (sel > 0) {
                    const uint2 pv = *(const uint2*)(g_hc + adr);
                    const __half2 p0 = *reinterpret_cast<const __half2*>(&pv.x);
                    const __half2 p1 = *reinterpret_cast<const __half2*>(&pv.y);
                    o0 += __low2float(p0);  o1 += __high2float(p0);
                    o2 += __low2float(p1);  o3 += __high2float(p1);
                }
                __half2 h0 = __floats2half2_rn(o0, o1);
                __half2 h1 = __floats2half2_rn(o2, o3);
                uint2 ov = make_uint2(*reinterpret_cast<uint32_t*>(&h0),
                                      *reinterpret_cast<uint32_t*>(&h1));
                *(uint2*)(g_hc + adr) = ov;
            } else {
                float4 o;
                o.x = s[0] + bv.x; o.y = s[1] + bv.y;
                o.z = s[2] + bv.z; o.w = s[3] + bv.w;
                *(float4*)(outF + m * 1024 + offc) = o;
            }
        }
        __syncwarp();
    }
#undef GLOADA
#undef GLOADB
#undef SCVT
}

// ---------------------------------------------------------------------------
// Partial sums of x (gating input); grid (8, 8, 4), 128 threads.
// ---------------------------------------------------------------------------
__global__ __launch_bounds__(128)
void psum_kernel(const float* __restrict__ X)
{
    const int b = blockIdx.x, cg = blockIdx.y, hg = blockIdx.z;
    const int c = cg * 128 + threadIdx.x;
    float sw[16], sd[16];
#pragma unroll
    for (int i = 0; i < 16; i++) { sw[i] = 0.0f; sd[i] = 0.0f; }
    float sp = 0.0f;
    const float* xb = X + (size_t)b * 4194304 + c;
    for (int hl = 0; hl < 4; hl++) {
        const int hh = hg * 4 + hl;
        float sh = 0.0f;
        const float* xh = xb + hh * 262144;
#pragma unroll
        for (int ww = 0; ww < 16; ww++)
#pragma unroll
            for (int dd = 0; dd < 16; dd++) {
                float v = xh[ww * 16384 + dd * 1024];
                sh += v; sw[ww] += v; sd[dd] += v;
            }
        g_smh[(b * 16 + hh) * 1024 + c] = sh;
        sp += sh;
    }
#pragma unroll
    for (int i = 0; i < 16; i++) {
        g_smw4[((hg * 8 + b) * 16 + i) * 1024 + c] = sw[i];
        g_smd4[((hg * 8 + b) * 16 + i) * 1024 + c] = sd[i];
    }
    g_sp4[(hg * 8 + b) * 1024 + c] = sp;
}

__global__ __launch_bounds__(64)
void wred_kernel(const float* __restrict__ w0, const float* __restrict__ w1,
                 const float* __restrict__ w2)
{
    const int kp = blockIdx.x, z = blockIdx.y, s = threadIdx.x;
    const float* W = (z == 0) ? w0 : (z == 1) ? w1 : w2;
    float acc = 0.0f;
#pragma unroll
    for (int p = 0; p < 16; p++) acc += W[kp * 1024 + p * 64 + s];
    g_sw[z * 65536 + kp * 64 + s] = acc;
}

__global__ __launch_bounds__(64)
void gate_kernel(const float* __restrict__ wc,
                 const float* __restrict__ bh, const float* __restrict__ bw,
                 const float* __restrict__ bd, const float* __restrict__ bc)
{
    __shared__ float smh[1024], smw[1024], smd[1024], spc[1024];
    const int b = blockIdx.x, sg = blockIdx.y, s = threadIdx.x;

    for (int i = s; i < 1024; i += 64) {
        const int kk = i >> 6, s2 = i & 63;
        smh[i] = g_smh[(b * 16 + kk) * 1024 + sg * 64 + s2];
        float aw = 0.0f, ad = 0.0f, ap = 0.0f;
#pragma unroll
        for (int g = 0; g < 4; g++) {
            aw += g_smw4[((g * 8 + b) * 16 + kk) * 1024 + sg * 64 + s2];
            ad += g_smd4[((g * 8 + b) * 16 + kk) * 1024 + sg * 64 + s2];
            ap += g_sp4[(g * 8 + b) * 1024 + i];
        }
        smw[i] = aw; smd[i] = ad; spc[i] = ap;
    }
    __syncthreads();

    float acc = 0.0f;
    for (int k = 0; k < 1024; k++)
        acc += smh[k] * g_sw[k * 64 + s]
             + smw[k] * g_sw[65536 + k * 64 + s]
             + smd[k] * g_sw[131072 + k * 64 + s];
    for (int cp = 0; cp < 1024; cp++)
        acc += spc[cp] * wc[cp * 1024 + sg * 64 + s];

    float bsum = 0.0f;
#pragma unroll
    for (int p = 0; p < 16; p++)
        bsum += bh[p * 64 + s] + bw[p * 64 + s] + bd[p * 64 + s];
    acc += 256.0f * bsum + 4096.0f * bc[sg * 64 + s];

    g_sum[b * 1024 + sg * 64 + s] = acc;
}

__global__ __launch_bounds__(1024)
void mlp1(const float* __restrict__ w1, const float* __restrict__ b1)
{
    __shared__ float sv[1024];
    __shared__ float red[4][256];
    const int b = blockIdx.x, tid = threadIdx.x;

    sv[tid] = g_sum[b * 1024 + tid] * (1.0f / 4096.0f);
    __syncthreads();

    const int o = tid & 255, part = tid >> 8;
    float acc = 0.0f;
    const float* wp = w1 + (part * 256) * 256 + o;
    const float* svp = sv + part * 256;
#pragma unroll 8
    for (int kk = 0; kk < 256; kk++) acc += svp[kk] * wp[kk * 256];
    red[part][o] = acc;
    __syncthreads();

    if (tid < 256) {
        float a = red[0][tid] + red[1][tid] + red[2][tid] + red[3][tid] + b1[tid];
        g_t[b * 256 + tid] = 0.5f * a * (1.0f + erff(a * 0.7071067811865476f));
    }
}

__global__ __launch_bounds__(256)
void mlp2(const float* __restrict__ w2, const float* __restrict__ b2)
{
    __shared__ float tt[256];
    __shared__ float zs[256];
    const int b = blockIdx.x, ny = blockIdx.y, tid = threadIdx.x;

    tt[tid] = g_t[b * 256 + tid];
    __syncthreads();

    const int n = ny * 256 + tid;
    float acc = b2[n];
#pragma unroll 8
    for (int k = 0; k < 256; k++) acc += tt[k] * w2[k * 4096 + n];
    zs[tid] = acc;
    __syncthreads();

    if (tid < 64) {
        const int c = ny * 64 + tid;
        const float v0 = zs[4*tid+0], v1 = zs[4*tid+1], v2 = zs[4*tid+2], v3 = zs[4*tid+3];
        const float mx = fmaxf(fmaxf(v0, v1), fmaxf(v2, v3));
        const float e0 = expf(v0-mx), e1 = expf(v1-mx), e2 = expf(v2-mx), e3 = expf(v3-mx);
        const float inv = 1.0f / (e0 + e1 + e2 + e3);
        g_a[0*8192 + b*1024 + c] = e0 * inv;
        g_a[1*8192 + b*1024 + c] = e1 * inv;
        g_a[2*8192 + b*1024 + c] = e2 * inv;
        g_a[3*8192 + b*1024 + c] = e3 * inv;
    }
}

// ---------------------------------------------------------------------------
extern "C" void kernel_launch(void* const* d_in, const int* in_sizes, int n_in,
                              void* d_out, int out_size)
{
    const float* x  = (const float*)d_in[0];
    const float* wh = (const float*)d_in[1];
    const float* bh = (const float*)d_in[2];
    const float* ww = (const float*)d_in[3];
    const float* bw = (const float*)d_in[4];
    const float* wd = (const float*)d_in[5];
    const float* bd = (const float*)d_in[6];
    const float* wc = (const float*)d_in[7];
    const float* bc = (const float*)d_in[8];
    const float* w1 = (const float*)d_in[9];
    const float* b1 = (const float*)d_in[10];
    const float* w2 = (const float*)d_in[11];
    const float* b2 = (const float*)d_in[12];
    const float* wp = (const float*)d_in[13];
    const float* bp = (const float*)d_in[14];
    float* out = (float*)d_out;

    // gating first (mean commutes with the GEMMs)
    psum_kernel<<<dim3(8, 8, 4), 128>>>(x);
    wred_kernel<<<dim3(1024, 3), 64>>>(wh, ww, wd);
    gate_kernel<<<dim3(8, 16), 64>>>(wc, bh, bw, bd, bc);
    mlp1<<<8, 1024>>>(w1, b1);
    mlp2<<<dim3(8, 16), 256>>>(w2, b2);

    dim3 grid(4, 256);
    // branch GEMMs with fused a_q-scale + fp16 RMW accumulate into g_hc;
    // h first (initializes comb), then w, d, c accumulate.
    gemm_mma<<<grid, 512>>>(x, wh, bh, 0, 64,     16384, 1024, 262144, nullptr);
    gemm_mma<<<grid, 512>>>(x, ww, bw, 1, 262144, 64,    1024, 16384,  nullptr);
    gemm_mma<<<grid, 512>>>(x, wd, bd, 2, 262144, 16384, 64,   1024,   nullptr);
    gemm_mma<<<grid, 512>>>(x, wc, bc, 3, 262144, 16384, 1024, 64,     nullptr);

    // final projection: plain GEMM on comb (fp16 A path)
    gemm_mma<<<grid, 512>>>(x, wp, bp, 4, 262144, 16384, 1024, 64, out);
}

// round 17
// speedup vs baseline: 3.8734x; 1.3029x over previous
#include <cuda_runtime.h>
#include <cuda_fp16.h>
#include <cstdint>
#include <math.h>

// ===========================================================================
// WeightedPermuteMLP — fp16 mma.sync + cp.async 3-stage pipeline, gating-first.
// X and weights pre-converted to fp16 (elementwise); GEMM loaders are pure
// cp.async (no register/cvt round-trip). D = A*B fp16, fp32 accum.
// rel_err ~4.9e-4 (gate 1e-3).
// ===========================================================================

#define NELEM 33554432

__device__ __align__(256) __half g_hc[NELEM];          // comb accumulator (fp16)
__device__ __align__(256) __half g_xf[NELEM];          // X in fp16
__device__ __align__(256) __half g_wf[5 * 1048576];    // weights fp16 [k][n]
__device__ __align__(256) float g_smh[8 * 16 * 1024];
__device__ __align__(256) float g_smw4[4 * 8 * 16 * 1024];
__device__ __align__(256) float g_smd4[4 * 8 * 16 * 1024];
__device__ __align__(256) float g_sp4[4 * 8 * 1024];
__device__ __align__(256) float g_sw[3 * 65536];
__device__ __align__(256) float g_sum[8 * 1024];
__device__ __align__(256) float g_t[8 * 256];
__device__ __align__(256) float g_a[4 * 8 * 1024];     // [q][b][chan]

__device__ __forceinline__ int row_base(int m, int s1, int s2, int s3) {
    return (m >> 12) * 4194304 + ((m >> 8) & 15) * s1 + ((m >> 4) & 15) * s2 + (m & 15) * s3;
}

__device__ __forceinline__ uint32_t s2u(const void* p) {
    uint32_t a;
    asm("{ .reg .u64 t; cvta.to.shared.u64 t, %1; cvt.u32.u64 %0, t; }" : "=r"(a) : "l"(p));
    return a;
}

#define LDSM4(R, ADDR) \
    asm volatile("ldmatrix.sync.aligned.m8n8.x4.shared.b16 {%0,%1,%2,%3}, [%4];" \
                 : "=r"((R)[0]), "=r"((R)[1]), "=r"((R)[2]), "=r"((R)[3]) : "r"(ADDR))
#define LDSM4T(R, ADDR) \
    asm volatile("ldmatrix.sync.aligned.m8n8.x4.trans.shared.b16 {%0,%1,%2,%3}, [%4];" \
                 : "=r"((R)[0]), "=r"((R)[1]), "=r"((R)[2]), "=r"((R)[3]) : "r"(ADDR))
#define MMA16816(D, A, B0, B1) \
    asm volatile("mma.sync.aligned.m16n8k16.row.col.f32.f16.f16.f32 " \
                 "{%0,%1,%2,%3}, {%4,%5,%6,%7}, {%8,%9}, {%0,%1,%2,%3};" \
                 : "+f"((D)[0]), "+f"((D)[1]), "+f"((D)[2]), "+f"((D)[3]) \
                 : "r"((A)[0]), "r"((A)[1]), "r"((A)[2]), "r"((A)[3]), "r"(B0), "r"(B1))

// ---------------------------------------------------------------------------
// fp32 -> fp16 elementwise converters (no layout change)
// ---------------------------------------------------------------------------
__global__ __launch_bounds__(256)
void cvtx_kernel(const float* __restrict__ X)
{
    const long i = ((long)blockIdx.x * 256 + threadIdx.x) * 8;
    float4 v0 = *(const float4*)(X + i);
    float4 v1 = *(const float4*)(X + i + 4);
    __half2 h0 = __floats2half2_rn(v0.x, v0.y);
    __half2 h1 = __floats2half2_rn(v0.z, v0.w);
    __half2 h2 = __floats2half2_rn(v1.x, v1.y);
    __half2 h3 = __floats2half2_rn(v1.z, v1.w);
    *(uint4*)(g_xf + i) = make_uint4(
        *reinterpret_cast<uint32_t*>(&h0), *reinterpret_cast<uint32_t*>(&h1),
        *reinterpret_cast<uint32_t*>(&h2), *reinterpret_cast<uint32_t*>(&h3));
}

__global__ __launch_bounds__(256)
void cvtw_kernel(const float* __restrict__ w0, const float* __restrict__ w1,
                 const float* __restrict__ w2, const float* __restrict__ w3,
                 const float* __restrict__ w4)
{
    const int z = blockIdx.y;
    const float* W = (z==0)?w0:(z==1)?w1:(z==2)?w2:(z==3)?w3:w4;
    const long i = ((long)blockIdx.x * 256 + threadIdx.x) * 8;
    float4 v0 = *(const float4*)(W + i);
    float4 v1 = *(const float4*)(W + i + 4);
    __half2 h0 = __floats2half2_rn(v0.x, v0.y);
    __half2 h1 = __floats2half2_rn(v0.z, v0.w);
    __half2 h2 = __floats2half2_rn(v1.x, v1.y);
    __half2 h3 = __floats2half2_rn(v1.z, v1.w);
    *(uint4*)(g_wf + ((long)z << 20) + i) = make_uint4(
        *reinterpret_cast<uint32_t*>(&h0), *reinterpret_cast<uint32_t*>(&h1),
        *reinterpret_cast<uint32_t*>(&h2), *reinterpret_cast<uint32_t*>(&h3));
}

// ---------------------------------------------------------------------------
// GEMM: block 128x256, BK=16, 512 thr, 16 warps (2m x 8n), warp tile 64x32.
// cp.async 3-stage pipeline; all operands fp16 in global.
//  sel 0..3 (h,w,d,c): A gather from g_xf; epilogue o=a_sel*(Z+bias), RMW g_hc.
//  sel 4: A = g_hc contiguous, write outF (fp32).
// ---------------------------------------------------------------------------
#define KPAD2 24
#define NPAD 264
#define A_ELE (128 * KPAD2)              // 3072 fp16
#define B_ELE (16 * NPAD)                // 4224 fp16
#define STG_ELE (A_ELE + B_ELE)          // 7296 fp16
#define STG_BYTES (STG_ELE * 2)          // 14592 B
#define OFF_B A_ELE
#define EPAD 36
#define SMEM_BYTES (3 * STG_BYTES)       // 43776 B

__global__ __launch_bounds__(512, 1)
void gemm_mma(const float* __restrict__ bias, int widx, int sel,
              int s1, int s2, int s3, int st, float* __restrict__ outF)
{
    __shared__ __align__(256) char smem[SMEM_BYTES];

    const int tid = threadIdx.x;
    const int wid = tid >> 5;
    const int lane = tid & 31;
    const int bm = blockIdx.y * 128;
    const int bn = blockIdx.x * 256;

    const __half* Ap = (sel < 4) ? g_xf : g_hc;
    const __half* Wf = g_wf + ((size_t)widx << 20);

    // ---- A loader: r=tid>>2 (row), lk=(tid&3)*4 (4 halves = 8B) ----
    const int r  = tid >> 2;
    const int lk = (tid & 3) * 4;
    const int abase = (sel < 4) ? (row_base(bm + r, s1, s2, s3) + lk)
                                : ((bm + r) * 1024 + lk);
    const uint32_t sAb = (uint32_t)(r * KPAD2 + lk) * 2;

    // ---- B loader: krow=tid>>5, ncol=(tid&31)*8 (8 halves = 16B) ----
    const int krow = tid >> 5;
    const int ncol = (tid & 31) * 8;
    const int bbase = krow * 1024 + bn + ncol;
    const uint32_t sBb = (uint32_t)(OFF_B + krow * NPAD + ncol) * 2;

    const uint32_t smem_u = s2u(smem);

#define CPA(T, STG) do {                                                       \
    const int aoff_ = (sel < 4) ? (((T) >> 2) * st + ((T) & 3) * 16)           \
                                : ((T) * 16);                                  \
    asm volatile("cp.async.ca.shared.global [%0], [%1], 8;"                    \
                 :: "r"(smem_u + (uint32_t)(STG) * STG_BYTES + sAb),           \
                    "l"(Ap + abase + aoff_));                                  \
    asm volatile("cp.async.cg.shared.global [%0], [%1], 16;"                   \
                 :: "r"(smem_u + (uint32_t)(STG) * STG_BYTES + sBb),           \
                    "l"(Wf + bbase + (T) * 16384));                            \
} while (0)
#define CP_COMMIT() asm volatile("cp.async.commit_group;" ::: "memory")
#define CP_WAIT1()  asm volatile("cp.async.wait_group 1;" ::: "memory")

    // ---- warp tiling: 2(m) x 8(n); warp tile 64x32 ----
    const int widm = wid >> 3;
    const int wm = widm * 64;
    const int wn = (wid & 7) * 32;

    const int frow = ((lane >> 3) & 1) * 8 + (lane & 7);
    const int fcol = (lane >> 4) * 8;
    uint32_t aAd[4], bAd[2];
#pragma unroll
    for (int mt = 0; mt < 4; mt++)
        aAd[mt] = smem_u + (uint32_t)(((wm + mt*16 + frow) * KPAD2 + fcol) * 2);
#pragma unroll
    for (int g = 0; g < 2; g++)
        bAd[g] = smem_u + OFF_B * 2
               + (uint32_t)((frow * NPAD + wn + g*16 + fcol) * 2);

    float acc[4][4][4];
#pragma unroll
    for (int mt = 0; mt < 4; mt++)
#pragma unroll
        for (int ng = 0; ng < 4; ng++)
#pragma unroll
            for (int q = 0; q < 4; q++) acc[mt][ng][q] = 0.0f;

    CPA(0, 0); CP_COMMIT();
    CPA(1, 1); CP_COMMIT();

    int stg = 0;          // stage of chunk t
    for (int t = 0; t < 64; t++) {
        CP_WAIT1();       // chunk t resident (t+1 may be in flight)
        __syncthreads();

        if (t + 2 < 64) {
            const int s2g = (stg + 2 >= 3) ? (stg - 1) : (stg + 2);
            CPA(t + 2, s2g);
        }
        CP_COMMIT();      // one group per iteration (possibly empty)

        {
            const uint32_t sb = (uint32_t)stg * STG_BYTES;
            uint32_t a[4][4], bh[2][4];
#pragma unroll
            for (int mt = 0; mt < 4; mt++) LDSM4(a[mt], aAd[mt] + sb);
            LDSM4T(bh[0], bAd[0] + sb);
            LDSM4T(bh[1], bAd[1] + sb);
#pragma unroll
            for (int mt = 0; mt < 4; mt++)
#pragma unroll
                for (int ng = 0; ng < 4; ng++)
                    MMA16816(acc[mt][ng], a[mt], bh[ng>>1][(ng&1)*2], bh[ng>>1][(ng&1)*2+1]);
        }

        stg = (stg + 1 == 3) ? 0 : (stg + 1);
    }
    __syncthreads();

    // ---- epilogue ----
    float* ep = (float*)smem + wid * (16 * EPAD);

    const int n0  = bn + wn;
    const int cc  = (lane & 7) * 4;
    const int offn = (n0 >> 6) * st + (n0 & 63) + cc;
    const int offc = n0 + cc;
    const float4 bv = *(const float4*)(bias + n0 + cc);

    const int er = lane >> 2;
    const int ec = 2 * (lane & 3);

    const int bq = bm >> 12;
    const int scol = (n0 & 63) + cc;
    const int by = blockIdx.y;
    const int sig0 = (by >> 1) & 15;
    const int sig1b = by * 8 + 4 * widm;

#pragma unroll
    for (int mt = 0; mt < 4; mt++) {
#pragma unroll
        for (int ng = 0; ng < 4; ng++) {
            float2 v0, v1;
            v0.x = acc[mt][ng][0]; v0.y = acc[mt][ng][1];
            v1.x = acc[mt][ng][2]; v1.y = acc[mt][ng][3];
            *(float2*)(ep + er * EPAD + ng*8 + ec) = v0;
            *(float2*)(ep + (er + 8) * EPAD + ng*8 + ec) = v1;
        }
        __syncwarp();
        const int sig_mt = (sig1b + mt) & 15;
#pragma unroll
        for (int i = 0; i < 4; i++) {
            const int rr = i * 4 + (lane >> 3);
            const int m = bm + wm + mt * 16 + rr;
            const float* s = ep + rr * EPAD + cc;
            if (sel < 4) {
                const int ch = (sel == 0) ? (sig0 * 64 + scol)
                             : (sel == 1) ? (sig_mt * 64 + scol)
                             : (sel == 2) ? (rr * 64 + scol)
                             : offc;
                const float4 av = *(const float4*)(g_a + (sel << 13) + (bq << 10) + ch);
                const int adr = row_base(m, s1, s2, s3) + offn;
                float o0 = av.x * (s[0] + bv.x);
                float o1 = av.y * (s[1] + bv.y);
                float o2 = av.z * (s[2] + bv.z);
                float o3 = av.w * (s[3] + bv.w);
                if (sel > 0) {
                    const uint2 pv = *(const uint2*)(g_hc + adr);
                    const __half2 p0 = *reinterpret_cast<const __half2*>(&pv.x);
                    const __half2 p1 = *reinterpret_cast<const __half2*>(&pv.y);
                    o0 += __low2float(p0);  o1 += __high2float(p0);
                    o2 += __low2float(p1);  o3 += __high2float(p1);
                }
                __half2 h0 = __floats2half2_rn(o0, o1);
                __half2 h1 = __floats2half2_rn(o2, o3);
                uint2 ov = make_uint2(*reinterpret_cast<uint32_t*>(&h0),
                                      *reinterpret_cast<uint32_t*>(&h1));
                *(uint2*)(g_hc + adr) = ov;
            } else {
                float4 o;
                o.x = s[0] + bv.x; o.y = s[1] + bv.y;
                o.z = s[2] + bv.z; o.w = s[3] + bv.w;
                *(float4*)(outF + m * 1024 + offc) = o;
            }
        }
        __syncwarp();
    }
#undef CPA
#undef CP_COMMIT
#undef CP_WAIT1
}

// ---------------------------------------------------------------------------
// Partial sums of x (gating input); grid (8, 8, 4), 128 threads.
// ---------------------------------------------------------------------------
__global__ __launch_bounds__(128)
void psum_kernel(const float* __restrict__ X)
{
    const int b = blockIdx.x, cg = blockIdx.y, hg = blockIdx.z;
    const int c = cg * 128 + threadIdx.x;
    float sw[16], sd[16];
#pragma unroll
    for (int i = 0; i < 16; i++) { sw[i] = 0.0f; sd[i] = 0.0f; }
    float sp = 0.0f;
    const float* xb = X + (size_t)b * 4194304 + c;
    for (int hl = 0; hl < 4; hl++) {
        const int hh = hg * 4 + hl;
        float sh = 0.0f;
        const float* xh = xb + hh * 262144;
#pragma unroll
        for (int ww = 0; ww < 16; ww++)
#pragma unroll
            for (int dd = 0; dd < 16; dd++) {
                float v = xh[ww * 16384 + dd * 1024];
                sh += v; sw[ww] += v; sd[dd] += v;
            }
        g_smh[(b * 16 + hh) * 1024 + c] = sh;
        sp += sh;
    }
#pragma unroll
    for (int i = 0; i < 16; i++) {
        g_smw4[((hg * 8 + b) * 16 + i) * 1024 + c] = sw[i];
        g_smd4[((hg * 8 + b) * 16 + i) * 1024 + c] = sd[i];
    }
    g_sp4[(hg * 8 + b) * 1024 + c] = sp;
}

__global__ __launch_bounds__(64)
void wred_kernel(const float* __restrict__ w0, const float* __restrict__ w1,
                 const float* __restrict__ w2)
{
    const int kp = blockIdx.x, z = blockIdx.y, s = threadIdx.x;
    const float* W = (z == 0) ? w0 : (z == 1) ? w1 : w2;
    float acc = 0.0f;
#pragma unroll
    for (int p = 0; p < 16; p++) acc += W[kp * 1024 + p * 64 + s];
    g_sw[z * 65536 + kp * 64 + s] = acc;
}

__global__ __launch_bounds__(64)
void gate_kernel(const float* __restrict__ wc,
                 const float* __restrict__ bh, const float* __restrict__ bw,
                 const float* __restrict__ bd, const float* __restrict__ bc)
{
    __shared__ float smh[1024], smw[1024], smd[1024], spc[1024];
    const int b = blockIdx.x, sg = blockIdx.y, s = threadIdx.x;

    for (int i = s; i < 1024; i += 64) {
        const int kk = i >> 6, s2 = i & 63;
        smh[i] = g_smh[(b * 16 + kk) * 1024 + sg * 64 + s2];
        float aw = 0.0f, ad = 0.0f, ap = 0.0f;
#pragma unroll
        for (int g = 0; g < 4; g++) {
            aw += g_smw4[((g * 8 + b) * 16 + kk) * 1024 + sg * 64 + s2];
            ad += g_smd4[((g * 8 + b) * 16 + kk) * 1024 + sg * 64 + s2];
            ap += g_sp4[(g * 8 + b) * 1024 + i];
        }
        smw[i] = aw; smd[i] = ad; spc[i] = ap;
    }
    __syncthreads();

    float acc = 0.0f;
    for (int k = 0; k < 1024; k++)
        acc += smh[k] * g_sw[k * 64 + s]
             + smw[k] * g_sw[65536 + k * 64 + s]
             + smd[k] * g_sw[131072 + k * 64 + s];
    for (int cp = 0; cp < 1024; cp++)
        acc += spc[cp] * wc[cp * 1024 + sg * 64 + s];

    float bsum = 0.0f;
#pragma unroll
    for (int p = 0; p < 16; p++)
        bsum += bh[p * 64 + s] + bw[p * 64 + s] + bd[p * 64 + s];
    acc += 256.0f * bsum + 4096.0f * bc[sg * 64 + s];

    g_sum[b * 1024 + sg * 64 + s] = acc;
}

__global__ __launch_bounds__(1024)
void mlp1(const float* __restrict__ w1, const float* __restrict__ b1)
{
    __shared__ float sv[1024];
    __shared__ float red[4][256];
    const int b = blockIdx.x, tid = threadIdx.x;

    sv[tid] = g_sum[b * 1024 + tid] * (1.0f / 4096.0f);
    __syncthreads();

    const int o = tid & 255, part = tid >> 8;
    float acc = 0.0f;
    const float* wp = w1 + (part * 256) * 256 + o;
    const float* svp = sv + part * 256;
#pragma unroll 8
    for (int kk = 0; kk < 256; kk++) acc += svp[kk] * wp[kk * 256];
    red[part][o] = acc;
    __syncthreads();

    if (tid < 256) {
        float a = red[0][tid] + red[1][tid] + red[2][tid] + red[3][tid] + b1[tid];
        g_t[b * 256 + tid] = 0.5f * a * (1.0f + erff(a * 0.7071067811865476f));
    }
}

__global__ __launch_bounds__(256)
void mlp2(const float* __restrict__ w2, const float* __restrict__ b2)
{
    __shared__ float tt[256];
    __shared__ float zs[256];
    const int b = blockIdx.x, ny = blockIdx.y, tid = threadIdx.x;

    tt[tid] = g_t[b * 256 + tid];
    __syncthreads();

    const int n = ny * 256 + tid;
    float acc = b2[n];
#pragma unroll 8
    for (int k = 0; k < 256; k++) acc += tt[k] * w2[k * 4096 + n];
    zs[tid] = acc;
    __syncthreads();

    if (tid < 64) {
        const int c = ny * 64 + tid;
        const float v0 = zs[4*tid+0], v1 = zs[4*tid+1], v2 = zs[4*tid+2], v3 = zs[4*tid+3];
        const float mx = fmaxf(fmaxf(v0, v1), fmaxf(v2, v3));
        const float e0 = expf(v0-mx), e1 = expf(v1-mx), e2 = expf(v2-mx), e3 = expf(v3-mx);
        const float inv = 1.0f / (e0 + e1 + e2 + e3);
        g_a[0*8192 + b*1024 + c] = e0 * inv;
        g_a[1*8192 + b*1024 + c] = e1 * inv;
        g_a[2*8192 + b*1024 + c] = e2 * inv;
        g_a[3*8192 + b*1024 + c] = e3 * inv;
    }
}

// ---------------------------------------------------------------------------
extern "C" void kernel_launch(void* const* d_in, const int* in_sizes, int n_in,
                              void* d_out, int out_size)
{
    const float* x  = (const float*)d_in[0];
    const float* wh = (const float*)d_in[1];
    const float* bh = (const float*)d_in[2];
    const float* ww = (const float*)d_in[3];
    const float* bw = (const float*)d_in[4];
    const float* wd = (const float*)d_in[5];
    const float* bd = (const float*)d_in[6];
    const float* wc = (const float*)d_in[7];
    const float* bc = (const float*)d_in[8];
    const float* w1 = (const float*)d_in[9];
    const float* b1 = (const float*)d_in[10];
    const float* w2 = (const float*)d_in[11];
    const float* b2 = (const float*)d_in[12];
    const float* wp = (const float*)d_in[13];
    const float* bp = (const float*)d_in[14];
    float* out = (float*)d_out;

    // fp16 conversions (elementwise, no layout change)
    cvtx_kernel<<<16384, 256>>>(x);
    cvtw_kernel<<<dim3(512, 5), 256>>>(wh, ww, wd, wc, wp);

    // gating first (mean commutes with the GEMMs) — exact fp32 path
    psum_kernel<<<dim3(8, 8, 4), 128>>>(x);
    wred_kernel<<<dim3(1024, 3), 64>>>(wh, ww, wd);
    gate_kernel<<<dim3(8, 16), 64>>>(wc, bh, bw, bd, bc);
    mlp1<<<8, 1024>>>(w1, b1);
    mlp2<<<dim3(8, 16), 256>>>(w2, b2);

    dim3 grid(4, 256);
    // branch GEMMs with fused a_q-scale + fp16 RMW accumulate into g_hc;
    // h first (initializes comb), then w, d, c accumulate.
    gemm_mma<<<grid, 512>>>(bh, 0, 0, 64,     16384, 1024, 262144, nullptr);
    gemm_mma<<<grid, 512>>>(bw, 1, 1, 262144, 64,    1024, 16384,  nullptr);
    gemm_mma<<<grid, 512>>>(bd, 2, 2, 262144, 16384, 64,   1024,   nullptr);
    gemm_mma<<<grid, 512>>>(bc, 3, 3, 262144, 16384, 1024, 64,     nullptr);

    // final projection: plain GEMM on comb (fp16 A path)
    gemm_mma<<<grid, 512>>>(bp, 4, 4, 262144, 16384, 1024, 64, out);
}